// round 2
// baseline (speedup 1.0000x reference)
#include <cuda_runtime.h>

// Problem dims
#define BB   128      // batch
#define TT   256      // time
#define HH   512      // hidden
#define GG   2048     // 4H gates
#define INN  1662     // input features
#define HD2  1024     // 2H
#define NC   100      // classes
#define BT   32768    // B*T

// ---------------- device scratch (allowed: __device__ globals) ----------------
__device__ float g_xpf[BT * GG];          // 256 MB: xproj fwd (also reused as tanh buf)
__device__ float g_xpb[BT * GG];          // 256 MB: xproj bwd (scan order)
__device__ float g_h0buf[BT * HD2];       // 128 MB: layer0 output [B,T,2H]
__device__ float g_outbuf[BT * HD2];      // 128 MB: layer1 output (lstm_out)
__device__ float g_z[2 * BB * GG];        // per-step gate preactivations (both dirs)
__device__ float g_hbuf[2 * BB * HH];
__device__ float g_cbuf[2 * BB * HH];
__device__ float g_scoresb[BT];
__device__ float g_attwb[BT];
__device__ float g_ctx[BB * HD2];
__device__ float g_hc[BB * HH];

// ---------------- grid barrier ----------------
__device__ unsigned g_bcount = 0;
__device__ unsigned g_bgen   = 0;

__device__ __forceinline__ void grid_barrier(unsigned nb) {
    __syncthreads();
    if (threadIdx.x == 0) {
        __threadfence();
        unsigned gen = atomicAdd(&g_bgen, 0u);
        if (atomicAdd(&g_bcount, 1u) == nb - 1u) {
            atomicExch(&g_bcount, 0u);
            __threadfence();
            atomicAdd(&g_bgen, 1u);
        } else {
            while (atomicAdd(&g_bgen, 0u) == gen) { __nanosleep(40); }
        }
    }
    __syncthreads();
}

// ---------------- generic tiled GEMM: C[M,N] = act(A*B + bias) ----------------
// TRANSB=1: B is [N,K] row-major (dot of rows).  TRANSB=0: B is [K,N] row-major.
// FLIP=1: A row r=(b,t) is read from (b, T-1-t)  (time reversal at GEMM time).
// ACT: 0=none, 1=tanh
template<int TRANSB, int FLIP, int ACT>
__global__ __launch_bounds__(256)
void gemm128(const float* __restrict__ A, const float* __restrict__ Bm,
             const float* __restrict__ bias, float* __restrict__ Cm,
             int M, int N, int K, int lda)
{
    __shared__ float As[16][128];
    __shared__ float Bs[16][128];

    const int tid = threadIdx.x;
    const int m0 = blockIdx.y * 128;
    const int n0 = blockIdx.x * 128;
    const int tm = tid >> 4;          // 0..15
    const int tn = tid & 15;          // 0..15

    float acc[8][8];
#pragma unroll
    for (int i = 0; i < 8; i++)
#pragma unroll
        for (int j = 0; j < 8; j++) acc[i][j] = 0.f;

    // A row mapping (time flip)
    const int ar  = tid >> 1;              // 0..127 (tile row)
    const int akh = (tid & 1) * 8;         // 0 or 8
    int gm = m0 + ar;
    int arow;
    if (FLIP) { int b = gm / TT; int t = gm % TT; arow = b * TT + (TT - 1 - t); }
    else      { arow = gm; }
    const float* Ap = A + (size_t)arow * lda;

    for (int k0 = 0; k0 < K; k0 += 16) {
        // load A tile (As[k][m])
#pragma unroll
        for (int i = 0; i < 8; i++) {
            int k = k0 + akh + i;
            As[akh + i][ar] = (k < K) ? Ap[k] : 0.f;
        }
        // load B tile (Bs[k][n])
        if (TRANSB) {
            const float* Bp = Bm + (size_t)(n0 + ar) * K;
#pragma unroll
            for (int i = 0; i < 8; i++) {
                int k = k0 + akh + i;
                Bs[akh + i][ar] = (k < K) ? Bp[k] : 0.f;
            }
        } else {
            int kr = tid >> 4;             // 0..15
            int ncs = (tid & 15) * 8;
            int k = k0 + kr;
            if (k < K) {
                const float* Bp = Bm + (size_t)k * N + n0 + ncs;
#pragma unroll
                for (int i = 0; i < 8; i++) Bs[kr][ncs + i] = Bp[i];
            } else {
#pragma unroll
                for (int i = 0; i < 8; i++) Bs[kr][ncs + i] = 0.f;
            }
        }
        __syncthreads();

#pragma unroll
        for (int k = 0; k < 16; k++) {
            float4 a0 = *(const float4*)&As[k][tm * 8];
            float4 a1 = *(const float4*)&As[k][tm * 8 + 4];
            float4 b0 = *(const float4*)&Bs[k][tn * 8];
            float4 b1 = *(const float4*)&Bs[k][tn * 8 + 4];
            float av[8] = {a0.x,a0.y,a0.z,a0.w,a1.x,a1.y,a1.z,a1.w};
            float bv[8] = {b0.x,b0.y,b0.z,b0.w,b1.x,b1.y,b1.z,b1.w};
#pragma unroll
            for (int i = 0; i < 8; i++)
#pragma unroll
                for (int j = 0; j < 8; j++) acc[i][j] += av[i] * bv[j];
        }
        __syncthreads();
    }

    const int mB = m0 + tm * 8;
    const int nB = n0 + tn * 8;
#pragma unroll
    for (int i = 0; i < 8; i++) {
        float* Cp = Cm + (size_t)(mB + i) * N + nB;
#pragma unroll
        for (int j = 0; j < 8; j++) {
            float v = acc[i][j] + bias[nB + j];
            if (ACT == 1) v = tanhf(v);
            Cp[j] = v;
        }
    }
}

// ---------------- persistent LSTM layer (both directions) ----------------
// xpF/xpB: [B,T,4H] in scan order. whF/whB: [4H,H]. hout: [B,T,2H].
__global__ __launch_bounds__(256, 1)
void lstm_layer(const float* __restrict__ xpF, const float* __restrict__ xpB,
                const float* __restrict__ whF, const float* __restrict__ whB,
                float* __restrict__ hout)
{
    const int tid = threadIdx.x;
    const int bi  = blockIdx.x;        // 0..127
    const unsigned NB = gridDim.x;     // 128
    const int gtid = bi * 256 + tid;   // 0..32767

    // zero h, c
    for (int i = gtid; i < 2 * BB * HH; i += (int)NB * 256) { g_hbuf[i] = 0.f; g_cbuf[i] = 0.f; }
    grid_barrier(NB);

    const int dir = bi >> 6;           // 0 fwd, 1 bwd
    const int sub = bi & 63;
    const int mt  = sub >> 5;          // 0..1  (batch tile of 64)
    const int nt  = sub & 31;          // 0..31 (gate-col tile of 64)
    const float* wh = dir ? whB : whF;
    const float* xp = dir ? xpB : xpF;
    const float* hvec = g_hbuf + dir * BB * HH;
    const int m0 = mt * 64, n0 = nt * 64;
    const int tm = tid >> 4, tn = tid & 15;

    __shared__ float As[16][64];
    __shared__ float Bs[16][64];

    const int lr  = tid >> 2;          // 0..63
    const int lkq = (tid & 3) * 4;     // 0,4,8,12

    for (int t = 0; t < TT; t++) {
        // ---- phase 1: z = h @ wh^T  (64x64 tile) ----
        float acc[4][4];
#pragma unroll
        for (int i = 0; i < 4; i++)
#pragma unroll
            for (int j = 0; j < 4; j++) acc[i][j] = 0.f;

        for (int k0 = 0; k0 < HH; k0 += 16) {
            float4 av = *(const float4*)(hvec + (m0 + lr) * HH + k0 + lkq);
            As[lkq + 0][lr] = av.x; As[lkq + 1][lr] = av.y;
            As[lkq + 2][lr] = av.z; As[lkq + 3][lr] = av.w;
            float4 bv = *(const float4*)(wh + (size_t)(n0 + lr) * HH + k0 + lkq);
            Bs[lkq + 0][lr] = bv.x; Bs[lkq + 1][lr] = bv.y;
            Bs[lkq + 2][lr] = bv.z; Bs[lkq + 3][lr] = bv.w;
            __syncthreads();
#pragma unroll
            for (int k = 0; k < 16; k++) {
                float4 a = *(const float4*)&As[k][tm * 4];
                float4 b = *(const float4*)&Bs[k][tn * 4];
                float avr[4] = {a.x,a.y,a.z,a.w};
                float bvr[4] = {b.x,b.y,b.z,b.w};
#pragma unroll
                for (int i = 0; i < 4; i++)
#pragma unroll
                    for (int j = 0; j < 4; j++) acc[i][j] += avr[i] * bvr[j];
            }
            __syncthreads();
        }
        {
            float* zd = g_z + dir * BB * GG;
#pragma unroll
            for (int i = 0; i < 4; i++) {
                int b = m0 + tm * 4 + i;
                const float* xr = xp + ((size_t)b * TT + t) * GG;
                float* zr = zd + (size_t)b * GG;
#pragma unroll
                for (int j = 0; j < 4; j++) {
                    int g = n0 + tn * 4 + j;
                    zr[g] = acc[i][j] + xr[g];
                }
            }
        }
        grid_barrier(NB);

        // ---- phase 2: gates ----
        {
            int u = gtid;
#pragma unroll
            for (int q = 0; q < 4; q++, u += (int)NB * 256) {
                int d2  = u >> 16;
                int rem = u & 65535;
                int b   = rem >> 9;
                int j   = rem & 511;
                const float* z = g_z + d2 * BB * GG + (size_t)b * GG;
                float zi = z[j], zf = z[HH + j], zg = z[2 * HH + j], zo = z[3 * HH + j];
                float si = 1.f / (1.f + __expf(-zi));
                float sf = 1.f / (1.f + __expf(-zf));
                float so = 1.f / (1.f + __expf(-zo));
                float tg = tanhf(zg);
                int idx = d2 * BB * HH + b * HH + j;
                float c = sf * g_cbuf[idx] + si * tg;
                float h = so * tanhf(c);
                g_cbuf[idx] = c;
                g_hbuf[idx] = h;
                int tt = d2 ? (TT - 1 - t) : t;
                hout[((size_t)b * TT + tt) * HD2 + d2 * HH + j] = h;
            }
        }
        grid_barrier(NB);
    }
}

// ---------------- tail kernels ----------------
__global__ void scores_k(const float* __restrict__ th, const float* __restrict__ aw2,
                         const float* __restrict__ ab2, float* __restrict__ sc)
{
    int r = blockIdx.x;
    const float* row = th + (size_t)r * HD2;
    float s = 0.f;
    for (int k = threadIdx.x; k < HD2; k += 128) s += row[k] * aw2[k];
    __shared__ float red[128];
    red[threadIdx.x] = s; __syncthreads();
    for (int o = 64; o > 0; o >>= 1) {
        if (threadIdx.x < o) red[threadIdx.x] += red[threadIdx.x + o];
        __syncthreads();
    }
    if (threadIdx.x == 0) sc[r] = red[0] + ab2[0];
}

__global__ void softmax_k(const float* __restrict__ sc, float* __restrict__ attw,
                          float* __restrict__ out_attw)
{
    int b = blockIdx.x, t = threadIdx.x;
    float v = sc[b * TT + t];
    __shared__ float red[TT];
    red[t] = v; __syncthreads();
    for (int o = 128; o > 0; o >>= 1) {
        if (t < o) red[t] = fmaxf(red[t], red[t + o]);
        __syncthreads();
    }
    float mx = red[0]; __syncthreads();
    float e = __expf(v - mx);
    red[t] = e; __syncthreads();
    for (int o = 128; o > 0; o >>= 1) {
        if (t < o) red[t] += red[t + o];
        __syncthreads();
    }
    float w = e / red[0];
    attw[b * TT + t] = w;
    if (out_attw) out_attw[b * TT + t] = w;
}

__global__ void context_k(const float* __restrict__ attw, const float* __restrict__ lo,
                          float* __restrict__ ctx)
{
    int b = blockIdx.y;
    int n = blockIdx.x * 256 + threadIdx.x;
    __shared__ float aw[TT];
    aw[threadIdx.x] = attw[b * TT + threadIdx.x];
    __syncthreads();
    float s = 0.f;
    const float* base = lo + (size_t)b * TT * HD2 + n;
#pragma unroll 4
    for (int t = 0; t < TT; t++) s += aw[t] * base[(size_t)t * HD2];
    ctx[b * HD2 + n] = s;
}

__global__ void cls1_k(const float* __restrict__ ctx, const float* __restrict__ w,
                       const float* __restrict__ bias, float* __restrict__ hc)
{
    int b = blockIdx.x, j = threadIdx.x;     // 512 threads
    __shared__ float xs[HD2];
    xs[j] = ctx[b * HD2 + j];
    xs[j + 512] = ctx[b * HD2 + j + 512];
    __syncthreads();
    float s = bias[j];
    for (int k = 0; k < HD2; k++) s += xs[k] * w[k * HH + j];
    hc[b * HH + j] = fmaxf(s, 0.f);
}

__global__ void cls2_k(const float* __restrict__ hc, const float* __restrict__ w,
                       const float* __restrict__ bias, float* __restrict__ out)
{
    int b = blockIdx.x, j = threadIdx.x;     // 128 threads, 100 active
    __shared__ float xs[HH];
    for (int k = j; k < HH; k += 128) xs[k] = hc[b * HH + k];
    __syncthreads();
    if (j < NC) {
        float s = bias[j];
        for (int k = 0; k < HH; k++) s += xs[k] * w[k * NC + j];
        out[b * NC + j] = s;
    }
}

// ---------------- launch ----------------
extern "C" void kernel_launch(void* const* d_in, const int* in_sizes, int n_in,
                              void* d_out, int out_size)
{
    const float* x     = (const float*)d_in[0];
    const float* wih0f = (const float*)d_in[1];
    const float* whh0f = (const float*)d_in[2];
    const float* b0f   = (const float*)d_in[3];
    const float* wih0b = (const float*)d_in[4];
    const float* whh0b = (const float*)d_in[5];
    const float* b0b   = (const float*)d_in[6];
    const float* wih1f = (const float*)d_in[7];
    const float* whh1f = (const float*)d_in[8];
    const float* b1f   = (const float*)d_in[9];
    const float* wih1b = (const float*)d_in[10];
    const float* whh1b = (const float*)d_in[11];
    const float* b1b   = (const float*)d_in[12];
    const float* aw1   = (const float*)d_in[13];
    const float* ab1   = (const float*)d_in[14];
    const float* aw2   = (const float*)d_in[15];
    const float* ab2   = (const float*)d_in[16];
    const float* cw1   = (const float*)d_in[17];
    const float* cb1   = (const float*)d_in[18];
    const float* cw2   = (const float*)d_in[19];
    const float* cb2   = (const float*)d_in[20];
    float* out = (float*)d_out;

    float *xpf, *xpb, *h0, *lo, *sc, *aw, *ctx, *hc;
    cudaGetSymbolAddress((void**)&xpf, g_xpf);
    cudaGetSymbolAddress((void**)&xpb, g_xpb);
    cudaGetSymbolAddress((void**)&h0,  g_h0buf);
    cudaGetSymbolAddress((void**)&lo,  g_outbuf);
    cudaGetSymbolAddress((void**)&sc,  g_scoresb);
    cudaGetSymbolAddress((void**)&aw,  g_attwb);
    cudaGetSymbolAddress((void**)&ctx, g_ctx);
    cudaGetSymbolAddress((void**)&hc,  g_hc);

    dim3 blk(256);
    dim3 gp(GG / 128, BT / 128);      // 16 x 256

    // layer 0 input projections (bwd written in scan order via FLIP)
    gemm128<1, 0, 0><<<gp, blk>>>(x, wih0f, b0f, xpf, BT, GG, INN, INN);
    gemm128<1, 1, 0><<<gp, blk>>>(x, wih0b, b0b, xpb, BT, GG, INN, INN);
    lstm_layer<<<128, 256>>>(xpf, xpb, whh0f, whh0b, h0);

    // layer 1 input projections
    gemm128<1, 0, 0><<<gp, blk>>>(h0, wih1f, b1f, xpf, BT, GG, HD2, HD2);
    gemm128<1, 1, 0><<<gp, blk>>>(h0, wih1b, b1b, xpb, BT, GG, HD2, HD2);
    lstm_layer<<<128, 256>>>(xpf, xpb, whh1f, whh1b, lo);

    // attention: tanh(lstm_out @ aw1 + ab1) -> reuse xpf as buffer
    dim3 ga(HD2 / 128, BT / 128);     // 8 x 256
    gemm128<0, 0, 1><<<ga, blk>>>(lo, aw1, ab1, xpf, BT, HD2, HD2, HD2);
    scores_k<<<BT, 128>>>(xpf, aw2, ab2, sc);

    float* out_attw = (out_size >= (BB * NC + BT)) ? (out + BB * NC) : nullptr;
    softmax_k<<<BB, TT>>>(sc, aw, out_attw);
    context_k<<<dim3(HD2 / 256, BB), 256>>>(aw, lo, ctx);
    cls1_k<<<BB, 512>>>(ctx, cw1, cb1, hc);
    cls2_k<<<BB, 128>>>(hc, cw2, cb2, out);
}

// round 4
// speedup vs baseline: 1.2045x; 1.2045x over previous
#include <cuda_runtime.h>
#include <cstdint>

// Problem dims
#define BB   128      // batch
#define TT   256      // time
#define HH   512      // hidden
#define GG   2048     // 4H gates
#define INN  1662     // input features
#define HD2  1024     // 2H
#define NC   100      // classes
#define BT   32768    // B*T

// ---------------- device scratch ----------------
__device__ float g_xpf[BT * GG];          // 256 MB: xproj fwd (reused as tanh buf)
__device__ float g_xpb[BT * GG];          // 256 MB: xproj bwd (scan order)
__device__ float g_h0buf[BT * HD2];       // 128 MB: layer0 output [B,T,2H]
__device__ float g_outbuf[BT * HD2];      // 128 MB: layer1 output (lstm_out)
__device__ float g_awt[HD2 * HD2];        // 4 MB: aw1 transposed [N,K]
__device__ float g_z[2 * BB * GG];
__device__ float g_hbuf[2 * BB * HH];
__device__ float g_cbuf[2 * BB * HH];
__device__ float g_scoresb[BT];
__device__ float g_attwb[BT];
__device__ float g_ctx[BB * HD2];
__device__ float g_hc[BB * HH];

// ---------------- grid barrier ----------------
__device__ unsigned g_bcount = 0;
__device__ unsigned g_bgen   = 0;

__device__ __forceinline__ void grid_barrier(unsigned nb) {
    __syncthreads();
    if (threadIdx.x == 0) {
        __threadfence();
        unsigned gen = atomicAdd(&g_bgen, 0u);
        if (atomicAdd(&g_bcount, 1u) == nb - 1u) {
            atomicExch(&g_bcount, 0u);
            __threadfence();
            atomicAdd(&g_bgen, 1u);
        } else {
            while (atomicAdd(&g_bgen, 0u) == gen) { __nanosleep(40); }
        }
    }
    __syncthreads();
}

__device__ __forceinline__ uint32_t f2tf32(float x) {
    uint32_t u;
    asm("cvt.rna.tf32.f32 %0, %1;" : "=r"(u) : "f"(x));
    return u;
}

__device__ __forceinline__ void mma_tf32(float* d, const uint32_t* a, const uint32_t* b) {
    asm volatile(
        "mma.sync.aligned.m16n8k8.row.col.f32.tf32.tf32.f32 "
        "{%0,%1,%2,%3}, {%4,%5,%6,%7}, {%8,%9}, {%0,%1,%2,%3};"
        : "+f"(d[0]), "+f"(d[1]), "+f"(d[2]), "+f"(d[3])
        : "r"(a[0]), "r"(a[1]), "r"(a[2]), "r"(a[3]), "r"(b[0]), "r"(b[1]));
}

// ---------------- tensor-core tf32 GEMM (mma.sync / HMMA) ----------------
// C[M,N] = act(A[M,K] * W[N,K]^T + bias).  Block tile 128x128, K chunk 32.
// 8 warps: 2 (m) x 4 (n); warp tile 64x32 -> 4 m16-tiles x 4 n8-tiles.
// FLIP=1: A row (b,t) read from (b, T-1-t).  ACT: 0=none, 1=tanh.
#define SSTR 36   // shared row stride (floats): bank = 4*row + col -> conflict-free frags

template<int FLIP, int ACT>
__global__ __launch_bounds__(256, 2)
void gemm_mma(const float* __restrict__ A, const float* __restrict__ W,
              const float* __restrict__ bias, float* __restrict__ C,
              int M, int N, int K)
{
    __shared__ uint32_t sA[128 * SSTR];
    __shared__ uint32_t sB[128 * SSTR];

    const int tid  = threadIdx.x;
    const int wid  = tid >> 5;
    const int lane = tid & 31;
    const int wm   = wid & 1;          // 0..1
    const int wn   = wid >> 1;         // 0..3
    const int m0 = blockIdx.y * 128;
    const int n0 = blockIdx.x * 128;

    const int lq = lane >> 2;          // 0..7
    const int lr = lane & 3;           // 0..3

    float acc[4][4][4];
#pragma unroll
    for (int i = 0; i < 4; i++)
#pragma unroll
        for (int j = 0; j < 4; j++)
#pragma unroll
            for (int r = 0; r < 4; r++) acc[i][j][r] = 0.f;

    const int nk = (K + 31) / 32;
    for (int kc = 0; kc < nk; kc++) {
        const int k0 = kc * 32;
        // ---- load tiles: 128 rows x 16 float2 segments each for A and B ----
#pragma unroll
        for (int i = 0; i < 8; i++) {
            int seg = tid + i * 256;          // 0..2047
            int r   = seg >> 4;               // 0..127
            int c2  = seg & 15;               // float2 col
            int k   = k0 + c2 * 2;
            int rem = K - k;

            // A
            int gm = m0 + r;
            int arow;
            if (FLIP) { int bI = gm >> 8; int t = gm & 255; arow = (bI << 8) + (255 - t); }
            else      { arow = gm; }
            float2 va = make_float2(0.f, 0.f);
            if (rem >= 2)      va = *(const float2*)(A + (size_t)arow * K + k);
            else if (rem == 1) va.x = A[(size_t)arow * K + k];
            sA[r * SSTR + c2 * 2]     = f2tf32(va.x);
            sA[r * SSTR + c2 * 2 + 1] = f2tf32(va.y);

            // B (= W rows as n)
            float2 vb = make_float2(0.f, 0.f);
            if (rem >= 2)      vb = *(const float2*)(W + (size_t)(n0 + r) * K + k);
            else if (rem == 1) vb.x = W[(size_t)(n0 + r) * K + k];
            sB[r * SSTR + c2 * 2]     = f2tf32(vb.x);
            sB[r * SSTR + c2 * 2 + 1] = f2tf32(vb.y);
        }
        __syncthreads();

        // ---- 4 k8 steps ----
#pragma unroll
        for (int ks = 0; ks < 4; ks++) {
            const int kb = ks * 8 + lr;
            uint32_t af[4][4];
#pragma unroll
            for (int mt = 0; mt < 4; mt++) {
                int base = wm * 64 + mt * 16 + lq;
                af[mt][0] = sA[ base      * SSTR + kb];
                af[mt][1] = sA[(base + 8) * SSTR + kb];
                af[mt][2] = sA[ base      * SSTR + kb + 4];
                af[mt][3] = sA[(base + 8) * SSTR + kb + 4];
            }
            uint32_t bf[4][2];
#pragma unroll
            for (int nt = 0; nt < 4; nt++) {
                int brow = wn * 32 + nt * 8 + lq;
                bf[nt][0] = sB[brow * SSTR + kb];
                bf[nt][1] = sB[brow * SSTR + kb + 4];
            }
#pragma unroll
            for (int mt = 0; mt < 4; mt++)
#pragma unroll
                for (int nt = 0; nt < 4; nt++)
                    mma_tf32(acc[mt][nt], af[mt], bf[nt]);
        }
        __syncthreads();
    }

    // ---- epilogue ----
    const int rbase = m0 + wm * 64;
    const int cbase = n0 + wn * 32;
#pragma unroll
    for (int mt = 0; mt < 4; mt++) {
#pragma unroll
        for (int nt = 0; nt < 4; nt++) {
            int c  = cbase + nt * 8 + lr * 2;
            float b0v = bias[c], b1v = bias[c + 1];
            int r0 = rbase + mt * 16 + lq;
            float v0 = acc[mt][nt][0] + b0v;
            float v1 = acc[mt][nt][1] + b1v;
            float v2 = acc[mt][nt][2] + b0v;
            float v3 = acc[mt][nt][3] + b1v;
            if (ACT == 1) { v0 = tanhf(v0); v1 = tanhf(v1); v2 = tanhf(v2); v3 = tanhf(v3); }
            *(float2*)(C + (size_t)r0 * N + c)       = make_float2(v0, v1);
            *(float2*)(C + (size_t)(r0 + 8) * N + c) = make_float2(v2, v3);
        }
    }
}

// ---------------- weight transpose (aw1 [K,N] -> [N,K]) ----------------
__global__ void transpose_k(const float* __restrict__ src, float* __restrict__ dst, int R, int Cc)
{
    __shared__ float t[32][33];
    int r0 = blockIdx.y * 32, c0 = blockIdx.x * 32;
    t[threadIdx.y][threadIdx.x] = src[(size_t)(r0 + threadIdx.y) * Cc + c0 + threadIdx.x];
    __syncthreads();
    dst[(size_t)(c0 + threadIdx.y) * R + r0 + threadIdx.x] = t[threadIdx.x][threadIdx.y];
}

// ---------------- persistent LSTM layer (both directions, fp32) ----------------
__global__ __launch_bounds__(256, 1)
void lstm_layer(const float* __restrict__ xpF, const float* __restrict__ xpB,
                const float* __restrict__ whF, const float* __restrict__ whB,
                float* __restrict__ hout)
{
    const int tid = threadIdx.x;
    const int bi  = blockIdx.x;        // 0..127
    const unsigned NB = gridDim.x;     // 128
    const int gtid = bi * 256 + tid;

    for (int i = gtid; i < 2 * BB * HH; i += (int)NB * 256) { g_hbuf[i] = 0.f; g_cbuf[i] = 0.f; }
    grid_barrier(NB);

    const int dir = bi >> 6;
    const int sub = bi & 63;
    const int mt  = sub >> 5;
    const int nt  = sub & 31;
    const float* wh = dir ? whB : whF;
    const float* xp = dir ? xpB : xpF;
    const float* hvec = g_hbuf + dir * BB * HH;
    const int m0 = mt * 64, n0 = nt * 64;
    const int tm = tid >> 4, tn = tid & 15;

    __shared__ float As[16][64];
    __shared__ float Bs[16][64];

    const int lr  = tid >> 2;
    const int lkq = (tid & 3) * 4;

    for (int t = 0; t < TT; t++) {
        float acc[4][4];
#pragma unroll
        for (int i = 0; i < 4; i++)
#pragma unroll
            for (int j = 0; j < 4; j++) acc[i][j] = 0.f;

        for (int k0 = 0; k0 < HH; k0 += 16) {
            float4 av = *(const float4*)(hvec + (m0 + lr) * HH + k0 + lkq);
            As[lkq + 0][lr] = av.x; As[lkq + 1][lr] = av.y;
            As[lkq + 2][lr] = av.z; As[lkq + 3][lr] = av.w;
            float4 bv = *(const float4*)(wh + (size_t)(n0 + lr) * HH + k0 + lkq);
            Bs[lkq + 0][lr] = bv.x; Bs[lkq + 1][lr] = bv.y;
            Bs[lkq + 2][lr] = bv.z; Bs[lkq + 3][lr] = bv.w;
            __syncthreads();
#pragma unroll
            for (int k = 0; k < 16; k++) {
                float4 a = *(const float4*)&As[k][tm * 4];
                float4 b = *(const float4*)&Bs[k][tn * 4];
                float avr[4] = {a.x,a.y,a.z,a.w};
                float bvr[4] = {b.x,b.y,b.z,b.w};
#pragma unroll
                for (int i = 0; i < 4; i++)
#pragma unroll
                    for (int j = 0; j < 4; j++) acc[i][j] += avr[i] * bvr[j];
            }
            __syncthreads();
        }
        {
            float* zd = g_z + dir * BB * GG;
#pragma unroll
            for (int i = 0; i < 4; i++) {
                int b = m0 + tm * 4 + i;
                const float* xr = xp + ((size_t)b * TT + t) * GG;
                float* zr = zd + (size_t)b * GG;
#pragma unroll
                for (int j = 0; j < 4; j++) {
                    int g = n0 + tn * 4 + j;
                    zr[g] = acc[i][j] + xr[g];
                }
            }
        }
        grid_barrier(NB);

        {
            int u = gtid;
#pragma unroll
            for (int q = 0; q < 4; q++, u += (int)NB * 256) {
                int d2  = u >> 16;
                int rem = u & 65535;
                int b   = rem >> 9;
                int j   = rem & 511;
                const float* z = g_z + d2 * BB * GG + (size_t)b * GG;
                float zi = z[j], zf = z[HH + j], zg = z[2 * HH + j], zo = z[3 * HH + j];
                float si = 1.f / (1.f + __expf(-zi));
                float sf = 1.f / (1.f + __expf(-zf));
                float so = 1.f / (1.f + __expf(-zo));
                float tg = tanhf(zg);
                int idx = d2 * BB * HH + b * HH + j;
                float c = sf * g_cbuf[idx] + si * tg;
                float h = so * tanhf(c);
                g_cbuf[idx] = c;
                g_hbuf[idx] = h;
                int tt = d2 ? (TT - 1 - t) : t;
                hout[((size_t)b * TT + tt) * HD2 + d2 * HH + j] = h;
            }
        }
        grid_barrier(NB);
    }
}

// ---------------- tail kernels ----------------
__global__ void scores_k(const float* __restrict__ th, const float* __restrict__ aw2,
                         const float* __restrict__ ab2, float* __restrict__ sc)
{
    int r = blockIdx.x;
    const float* row = th + (size_t)r * HD2;
    float s = 0.f;
    for (int k = threadIdx.x; k < HD2; k += 128) s += row[k] * aw2[k];
    __shared__ float red[128];
    red[threadIdx.x] = s; __syncthreads();
    for (int o = 64; o > 0; o >>= 1) {
        if (threadIdx.x < o) red[threadIdx.x] += red[threadIdx.x + o];
        __syncthreads();
    }
    if (threadIdx.x == 0) sc[r] = red[0] + ab2[0];
}

__global__ void softmax_k(const float* __restrict__ sc, float* __restrict__ attw,
                          float* __restrict__ out_attw)
{
    int b = blockIdx.x, t = threadIdx.x;
    float v = sc[b * TT + t];
    __shared__ float red[TT];
    red[t] = v; __syncthreads();
    for (int o = 128; o > 0; o >>= 1) {
        if (t < o) red[t] = fmaxf(red[t], red[t + o]);
        __syncthreads();
    }
    float mx = red[0]; __syncthreads();
    float e = __expf(v - mx);
    red[t] = e; __syncthreads();
    for (int o = 128; o > 0; o >>= 1) {
        if (t < o) red[t] += red[t + o];
        __syncthreads();
    }
    float w = e / red[0];
    attw[b * TT + t] = w;
    if (out_attw) out_attw[b * TT + t] = w;
}

__global__ void context_k(const float* __restrict__ attw, const float* __restrict__ lo,
                          float* __restrict__ ctx)
{
    int b = blockIdx.y;
    int n = blockIdx.x * 256 + threadIdx.x;
    __shared__ float aw[TT];
    aw[threadIdx.x] = attw[b * TT + threadIdx.x];
    __syncthreads();
    float s = 0.f;
    const float* base = lo + (size_t)b * TT * HD2 + n;
#pragma unroll 4
    for (int t = 0; t < TT; t++) s += aw[t] * base[(size_t)t * HD2];
    ctx[b * HD2 + n] = s;
}

__global__ void cls1_k(const float* __restrict__ ctx, const float* __restrict__ w,
                       const float* __restrict__ bias, float* __restrict__ hc)
{
    int b = blockIdx.x, j = threadIdx.x;
    __shared__ float xs[HD2];
    xs[j] = ctx[b * HD2 + j];
    xs[j + 512] = ctx[b * HD2 + j + 512];
    __syncthreads();
    float s = bias[j];
    for (int k = 0; k < HD2; k++) s += xs[k] * w[k * HH + j];
    hc[b * HH + j] = fmaxf(s, 0.f);
}

__global__ void cls2_k(const float* __restrict__ hc, const float* __restrict__ w,
                       const float* __restrict__ bias, float* __restrict__ out)
{
    int b = blockIdx.x, j = threadIdx.x;
    __shared__ float xs[HH];
    for (int k = j; k < HH; k += 128) xs[k] = hc[b * HH + k];
    __syncthreads();
    if (j < NC) {
        float s = bias[j];
        for (int k = 0; k < HH; k++) s += xs[k] * w[k * NC + j];
        out[b * NC + j] = s;
    }
}

// ---------------- launch ----------------
extern "C" void kernel_launch(void* const* d_in, const int* in_sizes, int n_in,
                              void* d_out, int out_size)
{
    const float* x     = (const float*)d_in[0];
    const float* wih0f = (const float*)d_in[1];
    const float* whh0f = (const float*)d_in[2];
    const float* b0f   = (const float*)d_in[3];
    const float* wih0b = (const float*)d_in[4];
    const float* whh0b = (const float*)d_in[5];
    const float* b0b   = (const float*)d_in[6];
    const float* wih1f = (const float*)d_in[7];
    const float* whh1f = (const float*)d_in[8];
    const float* b1f   = (const float*)d_in[9];
    const float* wih1b = (const float*)d_in[10];
    const float* whh1b = (const float*)d_in[11];
    const float* b1b   = (const float*)d_in[12];
    const float* aw1   = (const float*)d_in[13];
    const float* ab1   = (const float*)d_in[14];
    const float* aw2   = (const float*)d_in[15];
    const float* ab2   = (const float*)d_in[16];
    const float* cw1   = (const float*)d_in[17];
    const float* cb1   = (const float*)d_in[18];
    const float* cw2   = (const float*)d_in[19];
    const float* cb2   = (const float*)d_in[20];
    float* out = (float*)d_out;

    float *xpf, *xpb, *h0, *lo, *awt, *sc, *aw, *ctx, *hc;
    cudaGetSymbolAddress((void**)&xpf, g_xpf);
    cudaGetSymbolAddress((void**)&xpb, g_xpb);
    cudaGetSymbolAddress((void**)&h0,  g_h0buf);
    cudaGetSymbolAddress((void**)&lo,  g_outbuf);
    cudaGetSymbolAddress((void**)&awt, g_awt);
    cudaGetSymbolAddress((void**)&sc,  g_scoresb);
    cudaGetSymbolAddress((void**)&aw,  g_attwb);
    cudaGetSymbolAddress((void**)&ctx, g_ctx);
    cudaGetSymbolAddress((void**)&hc,  g_hc);

    // independent: transpose aw1 -> [N,K]
    transpose_k<<<dim3(HD2 / 32, HD2 / 32), dim3(32, 32)>>>(aw1, awt, HD2, HD2);

    dim3 blk(256);
    dim3 gp(GG / 128, BT / 128);      // 16 x 256

    // layer 0 input projections (HMMA tf32)
    gemm_mma<0, 0><<<gp, blk>>>(x, wih0f, b0f, xpf, BT, GG, INN);
    gemm_mma<1, 0><<<gp, blk>>>(x, wih0b, b0b, xpb, BT, GG, INN);
    lstm_layer<<<128, 256>>>(xpf, xpb, whh0f, whh0b, h0);

    // layer 1 input projections
    gemm_mma<0, 0><<<gp, blk>>>(h0, wih1f, b1f, xpf, BT, GG, HD2);
    gemm_mma<1, 0><<<gp, blk>>>(h0, wih1b, b1b, xpb, BT, GG, HD2);
    lstm_layer<<<128, 256>>>(xpf, xpb, whh1f, whh1b, lo);

    // attention: tanh(lstm_out @ aw1 + ab1) -> xpf (W = aw1^T)
    dim3 ga(HD2 / 128, BT / 128);     // 8 x 256
    gemm_mma<0, 1><<<ga, blk>>>(lo, awt, ab1, xpf, BT, HD2, HD2);
    scores_k<<<BT, 128>>>(xpf, aw2, ab2, sc);

    float* out_attw = (out_size >= (BB * NC + BT)) ? (out + BB * NC) : nullptr;
    softmax_k<<<BB, TT>>>(sc, aw, out_attw);
    context_k<<<dim3(HD2 / 256, BB), 256>>>(aw, lo, ctx);
    cls1_k<<<BB, 512>>>(ctx, cw1, cb1, hc);
    cls2_k<<<BB, 128>>>(hc, cw2, cb2, out);
}

// round 5
// speedup vs baseline: 1.5518x; 1.2884x over previous
#include <cuda_runtime.h>
#include <cstdint>

// Problem dims
#define BB   128      // batch
#define TT   256      // time
#define HH   512      // hidden
#define GG   2048     // 4H gates
#define INN  1662     // input features
#define HD2  1024     // 2H
#define NC   100      // classes
#define BT   32768    // B*T

// ---------------- device scratch ----------------
__device__ float g_xpf[BT * GG];          // 256 MB: xproj fwd (reused as tanh buf)
__device__ float g_xpb[BT * GG];          // 256 MB: xproj bwd (scan order)
__device__ float g_h0buf[BT * HD2];       // 128 MB: layer0 output [B,T,2H]
__device__ float g_outbuf[BT * HD2];      // 128 MB: layer1 output (lstm_out)
__device__ float g_awt[HD2 * HD2];        // 4 MB: aw1 transposed [N,K]
__device__ float g_hping[4 * BB * HH];    // ping-pong h: [ping][dir][B][H]
__device__ float g_scoresb[BT];
__device__ float g_attwb[BT];
__device__ float g_ctx[BB * HD2];
__device__ float g_hc[BB * HH];

// ---------------- grid barrier ----------------
__device__ unsigned g_bcount = 0;
__device__ unsigned g_bgen   = 0;

__device__ __forceinline__ void grid_barrier(unsigned nb) {
    __syncthreads();
    if (threadIdx.x == 0) {
        __threadfence();
        unsigned gen = atomicAdd(&g_bgen, 0u);
        if (atomicAdd(&g_bcount, 1u) == nb - 1u) {
            atomicExch(&g_bcount, 0u);
            __threadfence();
            atomicAdd(&g_bgen, 1u);
        } else {
            while (atomicAdd(&g_bgen, 0u) == gen) { __nanosleep(40); }
        }
    }
    __syncthreads();
}

__device__ __forceinline__ uint32_t f2tf32(float x) {
    uint32_t u;
    asm("cvt.rna.tf32.f32 %0, %1;" : "=r"(u) : "f"(x));
    return u;
}

__device__ __forceinline__ void mma_tf32(float* d, const uint32_t* a, const uint32_t* b) {
    asm volatile(
        "mma.sync.aligned.m16n8k8.row.col.f32.tf32.tf32.f32 "
        "{%0,%1,%2,%3}, {%4,%5,%6,%7}, {%8,%9}, {%0,%1,%2,%3};"
        : "+f"(d[0]), "+f"(d[1]), "+f"(d[2]), "+f"(d[3])
        : "r"(a[0]), "r"(a[1]), "r"(a[2]), "r"(a[3]), "r"(b[0]), "r"(b[1]));
}

// ---------------- tensor-core tf32 GEMM (mma.sync / HMMA) ----------------
// C[M,N] = act(A[M,K] * W[N,K]^T + bias).  Block tile 128x128, K chunk 32.
// 8 warps: 2 (m) x 4 (n); warp tile 64x32 -> 4 m16-tiles x 4 n8-tiles.
#define SSTR 36   // shared row stride (floats): conflict-free frags

template<int FLIP, int ACT>
__global__ __launch_bounds__(256, 2)
void gemm_mma(const float* __restrict__ A, const float* __restrict__ W,
              const float* __restrict__ bias, float* __restrict__ C,
              int M, int N, int K)
{
    __shared__ uint32_t sA[128 * SSTR];
    __shared__ uint32_t sB[128 * SSTR];

    const int tid  = threadIdx.x;
    const int wid  = tid >> 5;
    const int lane = tid & 31;
    const int wm   = wid & 1;
    const int wn   = wid >> 1;
    const int m0 = blockIdx.y * 128;
    const int n0 = blockIdx.x * 128;

    const int lq = lane >> 2;
    const int lr = lane & 3;

    float acc[4][4][4];
#pragma unroll
    for (int i = 0; i < 4; i++)
#pragma unroll
        for (int j = 0; j < 4; j++)
#pragma unroll
            for (int r = 0; r < 4; r++) acc[i][j][r] = 0.f;

    const int nk = (K + 31) / 32;
    for (int kc = 0; kc < nk; kc++) {
        const int k0 = kc * 32;
#pragma unroll
        for (int i = 0; i < 8; i++) {
            int seg = tid + i * 256;
            int r   = seg >> 4;
            int c2  = seg & 15;
            int k   = k0 + c2 * 2;
            int rem = K - k;

            int gm = m0 + r;
            int arow;
            if (FLIP) { int bI = gm >> 8; int t = gm & 255; arow = (bI << 8) + (255 - t); }
            else      { arow = gm; }
            float2 va = make_float2(0.f, 0.f);
            if (rem >= 2)      va = *(const float2*)(A + (size_t)arow * K + k);
            else if (rem == 1) va.x = A[(size_t)arow * K + k];
            sA[r * SSTR + c2 * 2]     = f2tf32(va.x);
            sA[r * SSTR + c2 * 2 + 1] = f2tf32(va.y);

            float2 vb = make_float2(0.f, 0.f);
            if (rem >= 2)      vb = *(const float2*)(W + (size_t)(n0 + r) * K + k);
            else if (rem == 1) vb.x = W[(size_t)(n0 + r) * K + k];
            sB[r * SSTR + c2 * 2]     = f2tf32(vb.x);
            sB[r * SSTR + c2 * 2 + 1] = f2tf32(vb.y);
        }
        __syncthreads();

#pragma unroll
        for (int ks = 0; ks < 4; ks++) {
            const int kb = ks * 8 + lr;
            uint32_t af[4][4];
#pragma unroll
            for (int mt = 0; mt < 4; mt++) {
                int base = wm * 64 + mt * 16 + lq;
                af[mt][0] = sA[ base      * SSTR + kb];
                af[mt][1] = sA[(base + 8) * SSTR + kb];
                af[mt][2] = sA[ base      * SSTR + kb + 4];
                af[mt][3] = sA[(base + 8) * SSTR + kb + 4];
            }
            uint32_t bf[4][2];
#pragma unroll
            for (int nt = 0; nt < 4; nt++) {
                int brow = wn * 32 + nt * 8 + lq;
                bf[nt][0] = sB[brow * SSTR + kb];
                bf[nt][1] = sB[brow * SSTR + kb + 4];
            }
#pragma unroll
            for (int mt = 0; mt < 4; mt++)
#pragma unroll
                for (int nt = 0; nt < 4; nt++)
                    mma_tf32(acc[mt][nt], af[mt], bf[nt]);
        }
        __syncthreads();
    }

    const int rbase = m0 + wm * 64;
    const int cbase = n0 + wn * 32;
#pragma unroll
    for (int mt = 0; mt < 4; mt++) {
#pragma unroll
        for (int nt = 0; nt < 4; nt++) {
            int c  = cbase + nt * 8 + lr * 2;
            float b0v = bias[c], b1v = bias[c + 1];
            int r0 = rbase + mt * 16 + lq;
            float v0 = acc[mt][nt][0] + b0v;
            float v1 = acc[mt][nt][1] + b1v;
            float v2 = acc[mt][nt][2] + b0v;
            float v3 = acc[mt][nt][3] + b1v;
            if (ACT == 1) { v0 = tanhf(v0); v1 = tanhf(v1); v2 = tanhf(v2); v3 = tanhf(v3); }
            *(float2*)(C + (size_t)r0 * N + c)       = make_float2(v0, v1);
            *(float2*)(C + (size_t)(r0 + 8) * N + c) = make_float2(v2, v3);
        }
    }
}

// ---------------- weight transpose (aw1 [K,N] -> [N,K]) ----------------
__global__ void transpose_k(const float* __restrict__ src, float* __restrict__ dst, int R, int Cc)
{
    __shared__ float t[32][33];
    int r0 = blockIdx.y * 32, c0 = blockIdx.x * 32;
    t[threadIdx.y][threadIdx.x] = src[(size_t)(r0 + threadIdx.y) * Cc + c0 + threadIdx.x];
    __syncthreads();
    dst[(size_t)(c0 + threadIdx.y) * R + r0 + threadIdx.x] = t[threadIdx.x][threadIdx.y];
}

// ---------------- tensor-core persistent LSTM (3xTF32 split) ----------------
// 128 blocks: dir = bid>>6, j0 = (bid&63)*8.  Block owns h columns [j0,j0+8)
// and its z columns are the 4 gate rows {g*512+j0..+7}.  W tile cached in
// shared (hi+lo) for the whole layer; h reloaded per step (ping-pong, __ldcg);
// z and c never leave the block. One grid barrier per step.
#define WSTR 516   // W shared stride (mod 32 == 4) -> conflict-free B frags
#define HSTR 68    // h chunk shared stride (mod 32 == 4)
#define SMEM_LSTM ((2 * 32 * WSTR + 2 * 128 * HSTR) * 4)

__global__ __launch_bounds__(256, 1)
void lstm_mma(const float* __restrict__ xpF, const float* __restrict__ xpB,
              const float* __restrict__ whF, const float* __restrict__ whB,
              float* __restrict__ hout)
{
    extern __shared__ uint32_t smem[];
    uint32_t* sWhi = smem;                      // 32 x WSTR
    uint32_t* sWlo = smem + 32 * WSTR;
    uint32_t* sHhi = smem + 2 * 32 * WSTR;      // 128 x HSTR
    uint32_t* sHlo = sHhi + 128 * HSTR;

    const int tid  = threadIdx.x;
    const int bi   = blockIdx.x;
    const unsigned NB = gridDim.x;
    const int w    = tid >> 5;
    const int lane = tid & 31;
    const int lq   = lane >> 2;
    const int lr   = lane & 3;
    const int dir  = bi >> 6;
    const int j0   = (bi & 63) * 8;
    const int w16  = w * 16;
    const float* wh = dir ? whB : whF;
    const float* xp = dir ? xpB : xpF;

    // load W tile (rows: gate g, col j0+jj -> shared row g*8+jj), split hi/lo
    for (int e = tid; e < 32 * 512; e += 256) {
        int n = e >> 9, k = e & 511;
        int grow = (n >> 3) * 512 + j0 + (n & 7);
        float v = wh[(size_t)grow * HH + k];
        uint32_t hi = f2tf32(v);
        uint32_t lo = f2tf32(v - __uint_as_float(hi));
        sWhi[n * WSTR + k] = hi;
        sWlo[n * WSTR + k] = lo;
    }
    __syncthreads();

    float creg[4] = {0.f, 0.f, 0.f, 0.f};

    for (int t = 0; t < TT; t++) {
        float acc[4][4];
#pragma unroll
        for (int nt = 0; nt < 4; nt++)
#pragma unroll
            for (int r = 0; r < 4; r++) acc[nt][r] = 0.f;

        if (t > 0) {
            const float* hprev = g_hping + ((((t - 1) & 1) << 1) + dir) * (BB * HH);
            for (int kc = 0; kc < 8; kc++) {
                __syncthreads();
#pragma unroll
                for (int it = 0; it < 8; it++) {
                    int seg = tid + it * 256;
                    int row = seg >> 4;
                    int col4 = (seg & 15) * 4;
                    float4 v = __ldcg((const float4*)(hprev + row * 512 + kc * 64 + col4));
                    uint32_t h0 = f2tf32(v.x), h1 = f2tf32(v.y), h2 = f2tf32(v.z), h3 = f2tf32(v.w);
                    uint32_t l0 = f2tf32(v.x - __uint_as_float(h0));
                    uint32_t l1 = f2tf32(v.y - __uint_as_float(h1));
                    uint32_t l2 = f2tf32(v.z - __uint_as_float(h2));
                    uint32_t l3 = f2tf32(v.w - __uint_as_float(h3));
                    *(uint4*)&sHhi[row * HSTR + col4] = make_uint4(h0, h1, h2, h3);
                    *(uint4*)&sHlo[row * HSTR + col4] = make_uint4(l0, l1, l2, l3);
                }
                __syncthreads();
#pragma unroll
                for (int ks = 0; ks < 8; ks++) {
                    const int kk = ks * 8 + lr;
                    uint32_t ahi[4], alo[4];
                    ahi[0] = sHhi[(w16 + lq)     * HSTR + kk];
                    ahi[1] = sHhi[(w16 + lq + 8) * HSTR + kk];
                    ahi[2] = sHhi[(w16 + lq)     * HSTR + kk + 4];
                    ahi[3] = sHhi[(w16 + lq + 8) * HSTR + kk + 4];
                    alo[0] = sHlo[(w16 + lq)     * HSTR + kk];
                    alo[1] = sHlo[(w16 + lq + 8) * HSTR + kk];
                    alo[2] = sHlo[(w16 + lq)     * HSTR + kk + 4];
                    alo[3] = sHlo[(w16 + lq + 8) * HSTR + kk + 4];
                    const int kg = kc * 64 + kk;
#pragma unroll
                    for (int nt = 0; nt < 4; nt++) {
                        uint32_t bhi[2], blo[2];
                        bhi[0] = sWhi[(nt * 8 + lq) * WSTR + kg];
                        bhi[1] = sWhi[(nt * 8 + lq) * WSTR + kg + 4];
                        blo[0] = sWlo[(nt * 8 + lq) * WSTR + kg];
                        blo[1] = sWlo[(nt * 8 + lq) * WSTR + kg + 4];
                        mma_tf32(acc[nt], ahi, bhi);
                        mma_tf32(acc[nt], alo, bhi);
                        mma_tf32(acc[nt], ahi, blo);
                    }
                }
            }
        }

        // epilogue: z = acc + xp; gates in registers; c in registers
        const int tt = dir ? (TT - 1 - t) : t;
        float* hnext = g_hping + (((t & 1) << 1) + dir) * (BB * HH);
#pragma unroll
        for (int bb = 0; bb < 2; bb++) {
            int b = w16 + lq + bb * 8;
            const float* xr = xp + ((size_t)b * TT + t) * GG + j0 + lr * 2;
            float2 xi = *(const float2*)(xr);
            float2 xf = *(const float2*)(xr + 512);
            float2 xg = *(const float2*)(xr + 1024);
            float2 xo = *(const float2*)(xr + 1536);
            int i0 = bb * 2;

            float zi = acc[0][i0] + xi.x, zf = acc[1][i0] + xf.x;
            float zg = acc[2][i0] + xg.x, zo = acc[3][i0] + xo.x;
            float si = 1.f / (1.f + __expf(-zi));
            float sf = 1.f / (1.f + __expf(-zf));
            float so = 1.f / (1.f + __expf(-zo));
            float tg = tanhf(zg);
            creg[i0] = sf * creg[i0] + si * tg;
            float h0v = so * tanhf(creg[i0]);

            zi = acc[0][i0 + 1] + xi.y; zf = acc[1][i0 + 1] + xf.y;
            zg = acc[2][i0 + 1] + xg.y; zo = acc[3][i0 + 1] + xo.y;
            si = 1.f / (1.f + __expf(-zi));
            sf = 1.f / (1.f + __expf(-zf));
            so = 1.f / (1.f + __expf(-zo));
            tg = tanhf(zg);
            creg[i0 + 1] = sf * creg[i0 + 1] + si * tg;
            float h1v = so * tanhf(creg[i0 + 1]);

            float2 hv = make_float2(h0v, h1v);
            *(float2*)(hnext + b * 512 + j0 + lr * 2) = hv;
            *(float2*)(hout + ((size_t)b * TT + tt) * HD2 + dir * 512 + j0 + lr * 2) = hv;
        }
        grid_barrier(NB);
    }
}

// ---------------- tail kernels ----------------
__global__ void scores_k(const float* __restrict__ th, const float* __restrict__ aw2,
                         const float* __restrict__ ab2, float* __restrict__ sc)
{
    int r = blockIdx.x;
    const float* row = th + (size_t)r * HD2;
    float s = 0.f;
    for (int k = threadIdx.x; k < HD2; k += 128) s += row[k] * aw2[k];
    __shared__ float red[128];
    red[threadIdx.x] = s; __syncthreads();
    for (int o = 64; o > 0; o >>= 1) {
        if (threadIdx.x < o) red[threadIdx.x] += red[threadIdx.x + o];
        __syncthreads();
    }
    if (threadIdx.x == 0) sc[r] = red[0] + ab2[0];
}

__global__ void softmax_k(const float* __restrict__ sc, float* __restrict__ attw,
                          float* __restrict__ out_attw)
{
    int b = blockIdx.x, t = threadIdx.x;
    float v = sc[b * TT + t];
    __shared__ float red[TT];
    red[t] = v; __syncthreads();
    for (int o = 128; o > 0; o >>= 1) {
        if (t < o) red[t] = fmaxf(red[t], red[t + o]);
        __syncthreads();
    }
    float mx = red[0]; __syncthreads();
    float e = __expf(v - mx);
    red[t] = e; __syncthreads();
    for (int o = 128; o > 0; o >>= 1) {
        if (t < o) red[t] += red[t + o];
        __syncthreads();
    }
    float w = e / red[0];
    attw[b * TT + t] = w;
    if (out_attw) out_attw[b * TT + t] = w;
}

__global__ void context_k(const float* __restrict__ attw, const float* __restrict__ lo,
                          float* __restrict__ ctx)
{
    int b = blockIdx.y;
    int n = blockIdx.x * 256 + threadIdx.x;
    __shared__ float aw[TT];
    aw[threadIdx.x] = attw[b * TT + threadIdx.x];
    __syncthreads();
    float s = 0.f;
    const float* base = lo + (size_t)b * TT * HD2 + n;
#pragma unroll 4
    for (int t = 0; t < TT; t++) s += aw[t] * base[(size_t)t * HD2];
    ctx[b * HD2 + n] = s;
}

__global__ void cls1_k(const float* __restrict__ ctx, const float* __restrict__ w,
                       const float* __restrict__ bias, float* __restrict__ hc)
{
    int b = blockIdx.x, j = threadIdx.x;
    __shared__ float xs[HD2];
    xs[j] = ctx[b * HD2 + j];
    xs[j + 512] = ctx[b * HD2 + j + 512];
    __syncthreads();
    float s = bias[j];
    for (int k = 0; k < HD2; k++) s += xs[k] * w[k * HH + j];
    hc[b * HH + j] = fmaxf(s, 0.f);
}

__global__ void cls2_k(const float* __restrict__ hc, const float* __restrict__ w,
                       const float* __restrict__ bias, float* __restrict__ out)
{
    int b = blockIdx.x, j = threadIdx.x;
    __shared__ float xs[HH];
    for (int k = j; k < HH; k += 128) xs[k] = hc[b * HH + k];
    __syncthreads();
    if (j < NC) {
        float s = bias[j];
        for (int k = 0; k < HH; k++) s += xs[k] * w[k * NC + j];
        out[b * NC + j] = s;
    }
}

// ---------------- launch ----------------
extern "C" void kernel_launch(void* const* d_in, const int* in_sizes, int n_in,
                              void* d_out, int out_size)
{
    const float* x     = (const float*)d_in[0];
    const float* wih0f = (const float*)d_in[1];
    const float* whh0f = (const float*)d_in[2];
    const float* b0f   = (const float*)d_in[3];
    const float* wih0b = (const float*)d_in[4];
    const float* whh0b = (const float*)d_in[5];
    const float* b0b   = (const float*)d_in[6];
    const float* wih1f = (const float*)d_in[7];
    const float* whh1f = (const float*)d_in[8];
    const float* b1f   = (const float*)d_in[9];
    const float* wih1b = (const float*)d_in[10];
    const float* whh1b = (const float*)d_in[11];
    const float* b1b   = (const float*)d_in[12];
    const float* aw1   = (const float*)d_in[13];
    const float* ab1   = (const float*)d_in[14];
    const float* aw2   = (const float*)d_in[15];
    const float* ab2   = (const float*)d_in[16];
    const float* cw1   = (const float*)d_in[17];
    const float* cb1   = (const float*)d_in[18];
    const float* cw2   = (const float*)d_in[19];
    const float* cb2   = (const float*)d_in[20];
    float* out = (float*)d_out;

    float *xpf, *xpb, *h0, *lo, *awt, *sc, *aw, *ctx, *hc;
    cudaGetSymbolAddress((void**)&xpf, g_xpf);
    cudaGetSymbolAddress((void**)&xpb, g_xpb);
    cudaGetSymbolAddress((void**)&h0,  g_h0buf);
    cudaGetSymbolAddress((void**)&lo,  g_outbuf);
    cudaGetSymbolAddress((void**)&awt, g_awt);
    cudaGetSymbolAddress((void**)&sc,  g_scoresb);
    cudaGetSymbolAddress((void**)&aw,  g_attwb);
    cudaGetSymbolAddress((void**)&ctx, g_ctx);
    cudaGetSymbolAddress((void**)&hc,  g_hc);

    cudaFuncSetAttribute(lstm_mma, cudaFuncAttributeMaxDynamicSharedMemorySize, SMEM_LSTM);

    // independent: transpose aw1 -> [N,K]
    transpose_k<<<dim3(HD2 / 32, HD2 / 32), dim3(32, 32)>>>(aw1, awt, HD2, HD2);

    dim3 blk(256);
    dim3 gp(GG / 128, BT / 128);      // 16 x 256

    // layer 0 input projections (HMMA tf32)
    gemm_mma<0, 0><<<gp, blk>>>(x, wih0f, b0f, xpf, BT, GG, INN);
    gemm_mma<1, 0><<<gp, blk>>>(x, wih0b, b0b, xpb, BT, GG, INN);
    lstm_mma<<<128, 256, SMEM_LSTM>>>(xpf, xpb, whh0f, whh0b, h0);

    // layer 1 input projections
    gemm_mma<0, 0><<<gp, blk>>>(h0, wih1f, b1f, xpf, BT, GG, HD2);
    gemm_mma<1, 0><<<gp, blk>>>(h0, wih1b, b1b, xpb, BT, GG, HD2);
    lstm_mma<<<128, 256, SMEM_LSTM>>>(xpf, xpb, whh1f, whh1b, lo);

    // attention: tanh(lstm_out @ aw1 + ab1) -> xpf (W = aw1^T)
    dim3 ga(HD2 / 128, BT / 128);     // 8 x 256
    gemm_mma<0, 1><<<ga, blk>>>(lo, awt, ab1, xpf, BT, HD2, HD2);
    scores_k<<<BT, 128>>>(xpf, aw2, ab2, sc);

    float* out_attw = (out_size >= (BB * NC + BT)) ? (out + BB * NC) : nullptr;
    softmax_k<<<BB, TT>>>(sc, aw, out_attw);
    context_k<<<dim3(HD2 / 256, BB), 256>>>(aw, lo, ctx);
    cls1_k<<<BB, 512>>>(ctx, cw1, cb1, hc);
    cls2_k<<<BB, 128>>>(hc, cw2, cb2, out);
}

// round 7
// speedup vs baseline: 2.8448x; 1.8332x over previous
#include <cuda_runtime.h>
#include <cstdint>

// Problem dims
#define BB   128      // batch
#define TT   256      // time
#define HH   512      // hidden
#define GG   2048     // 4H gates
#define INN  1662     // input features
#define HD2  1024     // 2H
#define NC   100      // classes
#define BT   32768    // B*T

// ---------------- device scratch ----------------
__device__ float g_xpf[BT * GG];
__device__ float g_xpb[BT * GG];
__device__ float g_h0buf[BT * HD2];
__device__ float g_outbuf[BT * HD2];
__device__ float g_awt[HD2 * HD2];
__device__ float g_hping[4 * BB * HH];    // ping-pong h: [ping][dir][B][H]
__device__ float g_scoresb[BT];
__device__ float g_attwb[BT];
__device__ float g_ctx[BB * HD2];
__device__ float g_hc[BB * HH];

// ---------------- grid barrier ----------------
__device__ unsigned g_bcount = 0;
__device__ unsigned g_bgen   = 0;

__device__ __forceinline__ void grid_barrier(unsigned nb) {
    __syncthreads();
    if (threadIdx.x == 0) {
        __threadfence();
        unsigned gen = atomicAdd(&g_bgen, 0u);
        if (atomicAdd(&g_bcount, 1u) == nb - 1u) {
            atomicExch(&g_bcount, 0u);
            __threadfence();
            atomicAdd(&g_bgen, 1u);
        } else {
            while (atomicAdd(&g_bgen, 0u) == gen) { __nanosleep(20); }
        }
    }
    __syncthreads();
}

__device__ __forceinline__ uint32_t f2tf32(float x) {
    uint32_t u;
    asm("cvt.rna.tf32.f32 %0, %1;" : "=r"(u) : "f"(x));
    return u;
}

__device__ __forceinline__ void mma_tf32(float* d, const uint32_t* a, const uint32_t* b) {
    asm volatile(
        "mma.sync.aligned.m16n8k8.row.col.f32.tf32.tf32.f32 "
        "{%0,%1,%2,%3}, {%4,%5,%6,%7}, {%8,%9}, {%0,%1,%2,%3};"
        : "+f"(d[0]), "+f"(d[1]), "+f"(d[2]), "+f"(d[3])
        : "r"(a[0]), "r"(a[1]), "r"(a[2]), "r"(a[3]), "r"(b[0]), "r"(b[1]));
}

__device__ __forceinline__ uint32_t smem_u32(const void* p) {
    uint32_t a;
    asm("{ .reg .u64 t; cvta.to.shared.u64 t, %1; cvt.u32.u64 %0, t; }" : "=r"(a) : "l"(p));
    return a;
}
__device__ __forceinline__ void cp_async16(uint32_t dst, const void* src, int src_bytes) {
    asm volatile("cp.async.cg.shared.global [%0], [%1], 16, %2;"
                 :: "r"(dst), "l"(src), "r"(src_bytes) : "memory");
}
__device__ __forceinline__ void cp_async8(uint32_t dst, const void* src, int src_bytes) {
    asm volatile("cp.async.ca.shared.global [%0], [%1], 8, %2;"
                 :: "r"(dst), "l"(src), "r"(src_bytes) : "memory");
}
__device__ __forceinline__ void cp_commit() {
    asm volatile("cp.async.commit_group;" ::: "memory");
}
__device__ __forceinline__ void cp_wait0() {
    asm volatile("cp.async.wait_group 0;" ::: "memory");
}

// ---------------- tensor-core tf32 GEMM, cp.async double-buffered ----------------
// C[M,N] = act(A[M,K] * W[N,K]^T + bias).  Block tile 128x128, K chunk 32.
// 8 warps: 2 (m) x 4 (n).  Raw fp32 staged in smem; cvt->tf32 at fragment load.
// Loader selected at runtime: 16B cp.async if K%4==0 (rows 16B-aligned),
// else 8B cp.async (requires K even -> rows 8B-aligned; INN=1662 qualifies).
#define SSTR 36
#define GSMEM (2 * 2 * 128 * SSTR * 4)   // 2 buffers x (A + B) raw fp32

template<int FLIP, int ACT>
__global__ __launch_bounds__(256, 2)
void gemm_mma(const float* __restrict__ A, const float* __restrict__ W,
              const float* __restrict__ bias, float* __restrict__ C,
              int M, int N, int K)
{
    extern __shared__ float dsm[];
    float* sA = dsm;                        // [2][128*SSTR]
    float* sB = dsm + 2 * 128 * SSTR;

    const int tid  = threadIdx.x;
    const int wid  = tid >> 5;
    const int lane = tid & 31;
    const int wm   = wid & 1;
    const int wn   = wid >> 1;
    const int m0 = blockIdx.y * 128;
    const int n0 = blockIdx.x * 128;
    const int lq = lane >> 2;
    const int lr = lane & 3;

    const uint32_t sA_base = smem_u32(sA);
    const uint32_t sB_base = smem_u32(sB);
    const bool use16 = ((K & 3) == 0);

    float acc[4][4][4];
#pragma unroll
    for (int i = 0; i < 4; i++)
#pragma unroll
        for (int j = 0; j < 4; j++)
#pragma unroll
            for (int r = 0; r < 4; r++) acc[i][j][r] = 0.f;

    const int nk = (K + 31) / 32;

    auto arow_of = [&](int r) {
        int gm = m0 + r;
        if (FLIP) { int bI = gm >> 8; int t = gm & 255; return (bI << 8) + (255 - t); }
        return gm;
    };

    // 16B loader: 128 rows x 8 float4 cols; 4 segs/thread/matrix
    auto load_chunk16 = [&](int kc, int buf) {
        const int k0 = kc * 32;
        const uint32_t boff = (uint32_t)buf * 128 * SSTR * 4;
#pragma unroll
        for (int i = 0; i < 4; i++) {
            int s  = tid + i * 256;
            int r  = s >> 3;
            int c4 = s & 7;
            int k  = k0 + c4 * 4;
            int nbf = K - k; nbf = nbf < 0 ? 0 : (nbf > 4 ? 4 : nbf);
            int bytes = nbf * 4;
            int ksrc = (k < K) ? k : 0;               // aligned clamp
            uint32_t soff = (uint32_t)(r * SSTR + c4 * 4) * 4;
            cp_async16(sA_base + boff + soff, A + (size_t)arow_of(r) * K + ksrc, bytes);
            cp_async16(sB_base + boff + soff, W + (size_t)(n0 + r) * K + ksrc, bytes);
        }
        cp_commit();
    };

    // 8B loader: 128 rows x 16 float2 cols; 8 segs/thread/matrix
    auto load_chunk8 = [&](int kc, int buf) {
        const int k0 = kc * 32;
        const uint32_t boff = (uint32_t)buf * 128 * SSTR * 4;
#pragma unroll
        for (int i = 0; i < 8; i++) {
            int s  = tid + i * 256;
            int r  = s >> 4;
            int c2 = s & 15;
            int k  = k0 + c2 * 2;
            int nbf = K - k; nbf = nbf < 0 ? 0 : (nbf > 2 ? 2 : nbf);
            int bytes = nbf * 4;
            int ksrc = (k < K) ? k : 0;               // aligned clamp (k even)
            uint32_t soff = (uint32_t)(r * SSTR + c2 * 2) * 4;
            cp_async8(sA_base + boff + soff, A + (size_t)arow_of(r) * K + ksrc, bytes);
            cp_async8(sB_base + boff + soff, W + (size_t)(n0 + r) * K + ksrc, bytes);
        }
        cp_commit();
    };

    auto load_chunk = [&](int kc, int buf) {
        if (use16) load_chunk16(kc, buf); else load_chunk8(kc, buf);
    };

    load_chunk(0, 0);

    for (int kc = 0; kc < nk; kc++) {
        cp_wait0();
        __syncthreads();
        if (kc + 1 < nk) load_chunk(kc + 1, (kc + 1) & 1);

        const float* bA = sA + (kc & 1) * 128 * SSTR;
        const float* bB = sB + (kc & 1) * 128 * SSTR;
#pragma unroll
        for (int ks = 0; ks < 4; ks++) {
            const int kb = ks * 8 + lr;
            uint32_t af[4][4];
#pragma unroll
            for (int mt = 0; mt < 4; mt++) {
                int base = wm * 64 + mt * 16 + lq;
                af[mt][0] = f2tf32(bA[ base      * SSTR + kb]);
                af[mt][1] = f2tf32(bA[(base + 8) * SSTR + kb]);
                af[mt][2] = f2tf32(bA[ base      * SSTR + kb + 4]);
                af[mt][3] = f2tf32(bA[(base + 8) * SSTR + kb + 4]);
            }
            uint32_t bf[4][2];
#pragma unroll
            for (int nt = 0; nt < 4; nt++) {
                int brow = wn * 32 + nt * 8 + lq;
                bf[nt][0] = f2tf32(bB[brow * SSTR + kb]);
                bf[nt][1] = f2tf32(bB[brow * SSTR + kb + 4]);
            }
#pragma unroll
            for (int mt = 0; mt < 4; mt++)
#pragma unroll
                for (int nt = 0; nt < 4; nt++)
                    mma_tf32(acc[mt][nt], af[mt], bf[nt]);
        }
        __syncthreads();
    }

    const int rbase = m0 + wm * 64;
    const int cbase = n0 + wn * 32;
#pragma unroll
    for (int mt = 0; mt < 4; mt++) {
#pragma unroll
        for (int nt = 0; nt < 4; nt++) {
            int c  = cbase + nt * 8 + lr * 2;
            float b0v = bias[c], b1v = bias[c + 1];
            int r0 = rbase + mt * 16 + lq;
            float v0 = acc[mt][nt][0] + b0v;
            float v1 = acc[mt][nt][1] + b1v;
            float v2 = acc[mt][nt][2] + b0v;
            float v3 = acc[mt][nt][3] + b1v;
            if (ACT == 1) { v0 = tanhf(v0); v1 = tanhf(v1); v2 = tanhf(v2); v3 = tanhf(v3); }
            *(float2*)(C + (size_t)r0 * N + c)       = make_float2(v0, v1);
            *(float2*)(C + (size_t)(r0 + 8) * N + c) = make_float2(v2, v3);
        }
    }
}

// ---------------- weight transpose ----------------
__global__ void transpose_k(const float* __restrict__ src, float* __restrict__ dst, int R, int Cc)
{
    __shared__ float t[32][33];
    int r0 = blockIdx.y * 32, c0 = blockIdx.x * 32;
    t[threadIdx.y][threadIdx.x] = src[(size_t)(r0 + threadIdx.y) * Cc + c0 + threadIdx.x];
    __syncthreads();
    dst[(size_t)(c0 + threadIdx.y) * R + r0 + threadIdx.x] = t[threadIdx.x][threadIdx.y];
}

// ---------------- tensor-core persistent LSTM (3xTF32 split, cp.async h) ----------------
// 128 blocks: dir = bid>>6, j0 = (bid&63)*8.  W tile resident in smem (hi+lo tf32).
// h chunk (64 cols) staged raw fp32 via cp.async (16B aligned), double-buffered;
// hi/lo derived at fragment-load time.  One grid barrier per step.
#define WSTR 516
#define HSTR 68
#define SMEM_LSTM ((2 * 32 * WSTR) * 4 + (2 * 128 * HSTR) * 4)

__global__ __launch_bounds__(256, 1)
void lstm_mma(const float* __restrict__ xpF, const float* __restrict__ xpB,
              const float* __restrict__ whF, const float* __restrict__ whB,
              float* __restrict__ hout)
{
    extern __shared__ uint32_t smem[];
    uint32_t* sWhi = smem;                      // 32 x WSTR (tf32)
    uint32_t* sWlo = smem + 32 * WSTR;
    float* sH = (float*)(smem + 2 * 32 * WSTR); // [2][128*HSTR] raw fp32

    const int tid  = threadIdx.x;
    const int bi   = blockIdx.x;
    const unsigned NB = gridDim.x;
    const int w    = tid >> 5;
    const int lane = tid & 31;
    const int lq   = lane >> 2;
    const int lr   = lane & 3;
    const int dir  = bi >> 6;
    const int j0   = (bi & 63) * 8;
    const int w16  = w * 16;
    const float* wh = dir ? whB : whF;
    const float* xp = dir ? xpB : xpF;
    const uint32_t sH_base = smem_u32(sH);

    // load W tile (gate-row layout), split hi/lo once
    for (int e = tid; e < 32 * 512; e += 256) {
        int n = e >> 9, k = e & 511;
        int grow = (n >> 3) * 512 + j0 + (n & 7);
        float v = wh[(size_t)grow * HH + k];
        uint32_t hi = f2tf32(v);
        uint32_t lo = f2tf32(v - __uint_as_float(hi));
        sWhi[n * WSTR + k] = hi;
        sWlo[n * WSTR + k] = lo;
    }
    __syncthreads();

    float creg[4] = {0.f, 0.f, 0.f, 0.f};

    for (int t = 0; t < TT; t++) {
        // prefetch xproj values for this step (overlaps with MMA chunks)
        float2 xg2[2][4];
#pragma unroll
        for (int bb = 0; bb < 2; bb++) {
            const float* xr = xp + ((size_t)(w16 + lq + bb * 8) * TT + t) * GG + j0 + lr * 2;
            xg2[bb][0] = *(const float2*)(xr);
            xg2[bb][1] = *(const float2*)(xr + 512);
            xg2[bb][2] = *(const float2*)(xr + 1024);
            xg2[bb][3] = *(const float2*)(xr + 1536);
        }

        float acc[4][4];
#pragma unroll
        for (int nt = 0; nt < 4; nt++)
#pragma unroll
            for (int r = 0; r < 4; r++) acc[nt][r] = 0.f;

        if (t > 0) {
            const float* hprev = g_hping + ((((t - 1) & 1) << 1) + dir) * (BB * HH);

            auto load_hchunk = [&](int kc, int buf) {
                const uint32_t boff = (uint32_t)buf * 128 * HSTR * 4;
#pragma unroll
                for (int i = 0; i < 8; i++) {
                    int s   = tid + i * 256;
                    int row = s >> 4;
                    int c4  = s & 15;
                    cp_async16(sH_base + boff + (uint32_t)(row * HSTR + c4 * 4) * 4,
                               hprev + row * 512 + kc * 64 + c4 * 4, 16);
                }
                cp_commit();
            };

            load_hchunk(0, 0);
            for (int kc = 0; kc < 8; kc++) {
                cp_wait0();
                __syncthreads();
                if (kc < 7) load_hchunk(kc + 1, (kc + 1) & 1);

                const float* bH = sH + (kc & 1) * 128 * HSTR;
#pragma unroll
                for (int ks = 0; ks < 8; ks++) {
                    const int kk = ks * 8 + lr;
                    float v0 = bH[(w16 + lq)     * HSTR + kk];
                    float v1 = bH[(w16 + lq + 8) * HSTR + kk];
                    float v2 = bH[(w16 + lq)     * HSTR + kk + 4];
                    float v3 = bH[(w16 + lq + 8) * HSTR + kk + 4];
                    uint32_t ahi[4], alo[4];
                    ahi[0] = f2tf32(v0); alo[0] = f2tf32(v0 - __uint_as_float(ahi[0]));
                    ahi[1] = f2tf32(v1); alo[1] = f2tf32(v1 - __uint_as_float(ahi[1]));
                    ahi[2] = f2tf32(v2); alo[2] = f2tf32(v2 - __uint_as_float(ahi[2]));
                    ahi[3] = f2tf32(v3); alo[3] = f2tf32(v3 - __uint_as_float(ahi[3]));
                    const int kg = kc * 64 + kk;
#pragma unroll
                    for (int nt = 0; nt < 4; nt++) {
                        uint32_t bhi[2], blo[2];
                        bhi[0] = sWhi[(nt * 8 + lq) * WSTR + kg];
                        bhi[1] = sWhi[(nt * 8 + lq) * WSTR + kg + 4];
                        blo[0] = sWlo[(nt * 8 + lq) * WSTR + kg];
                        blo[1] = sWlo[(nt * 8 + lq) * WSTR + kg + 4];
                        mma_tf32(acc[nt], ahi, bhi);
                        mma_tf32(acc[nt], alo, bhi);
                        mma_tf32(acc[nt], ahi, blo);
                    }
                }
                __syncthreads();
            }
        }

        // epilogue: gates + c in registers
        const int tt = dir ? (TT - 1 - t) : t;
        float* hnext = g_hping + (((t & 1) << 1) + dir) * (BB * HH);
#pragma unroll
        for (int bb = 0; bb < 2; bb++) {
            int b = w16 + lq + bb * 8;
            int i0 = bb * 2;

            float zi = acc[0][i0] + xg2[bb][0].x, zf = acc[1][i0] + xg2[bb][1].x;
            float zg = acc[2][i0] + xg2[bb][2].x, zo = acc[3][i0] + xg2[bb][3].x;
            float si = 1.f / (1.f + __expf(-zi));
            float sf = 1.f / (1.f + __expf(-zf));
            float so = 1.f / (1.f + __expf(-zo));
            float tg = tanhf(zg);
            creg[i0] = sf * creg[i0] + si * tg;
            float h0v = so * tanhf(creg[i0]);

            zi = acc[0][i0 + 1] + xg2[bb][0].y; zf = acc[1][i0 + 1] + xg2[bb][1].y;
            zg = acc[2][i0 + 1] + xg2[bb][2].y; zo = acc[3][i0 + 1] + xg2[bb][3].y;
            si = 1.f / (1.f + __expf(-zi));
            sf = 1.f / (1.f + __expf(-zf));
            so = 1.f / (1.f + __expf(-zo));
            tg = tanhf(zg);
            creg[i0 + 1] = sf * creg[i0 + 1] + si * tg;
            float h1v = so * tanhf(creg[i0 + 1]);

            float2 hv = make_float2(h0v, h1v);
            *(float2*)(hnext + b * 512 + j0 + lr * 2) = hv;
            *(float2*)(hout + ((size_t)b * TT + tt) * HD2 + dir * 512 + j0 + lr * 2) = hv;
        }
        grid_barrier(NB);
    }
}

// ---------------- tail kernels ----------------
__global__ void scores_k(const float* __restrict__ th, const float* __restrict__ aw2,
                         const float* __restrict__ ab2, float* __restrict__ sc)
{
    int r = blockIdx.x;
    const float* row = th + (size_t)r * HD2;
    float s = 0.f;
    for (int k = threadIdx.x; k < HD2; k += 128) s += row[k] * aw2[k];
    __shared__ float red[128];
    red[threadIdx.x] = s; __syncthreads();
    for (int o = 64; o > 0; o >>= 1) {
        if (threadIdx.x < o) red[threadIdx.x] += red[threadIdx.x + o];
        __syncthreads();
    }
    if (threadIdx.x == 0) sc[r] = red[0] + ab2[0];
}

__global__ void softmax_k(const float* __restrict__ sc, float* __restrict__ attw,
                          float* __restrict__ out_attw)
{
    int b = blockIdx.x, t = threadIdx.x;
    float v = sc[b * TT + t];
    __shared__ float red[TT];
    red[t] = v; __syncthreads();
    for (int o = 128; o > 0; o >>= 1) {
        if (t < o) red[t] = fmaxf(red[t], red[t + o]);
        __syncthreads();
    }
    float mx = red[0]; __syncthreads();
    float e = __expf(v - mx);
    red[t] = e; __syncthreads();
    for (int o = 128; o > 0; o >>= 1) {
        if (t < o) red[t] += red[t + o];
        __syncthreads();
    }
    float w = e / red[0];
    attw[b * TT + t] = w;
    if (out_attw) out_attw[b * TT + t] = w;
}

__global__ void context_k(const float* __restrict__ attw, const float* __restrict__ lo,
                          float* __restrict__ ctx)
{
    int b = blockIdx.y;
    int n = blockIdx.x * 256 + threadIdx.x;
    __shared__ float aw[TT];
    aw[threadIdx.x] = attw[b * TT + threadIdx.x];
    __syncthreads();
    float s = 0.f;
    const float* base = lo + (size_t)b * TT * HD2 + n;
#pragma unroll 4
    for (int t = 0; t < TT; t++) s += aw[t] * base[(size_t)t * HD2];
    ctx[b * HD2 + n] = s;
}

__global__ void cls1_k(const float* __restrict__ ctx, const float* __restrict__ w,
                       const float* __restrict__ bias, float* __restrict__ hc)
{
    int b = blockIdx.x, j = threadIdx.x;
    __shared__ float xs[HD2];
    xs[j] = ctx[b * HD2 + j];
    xs[j + 512] = ctx[b * HD2 + j + 512];
    __syncthreads();
    float s = bias[j];
    for (int k = 0; k < HD2; k++) s += xs[k] * w[k * HH + j];
    hc[b * HH + j] = fmaxf(s, 0.f);
}

__global__ void cls2_k(const float* __restrict__ hc, const float* __restrict__ w,
                       const float* __restrict__ bias, float* __restrict__ out)
{
    int b = blockIdx.x, j = threadIdx.x;
    __shared__ float xs[HH];
    for (int k = j; k < HH; k += 128) xs[k] = hc[b * HH + k];
    __syncthreads();
    if (j < NC) {
        float s = bias[j];
        for (int k = 0; k < HH; k++) s += xs[k] * w[k * NC + j];
        out[b * NC + j] = s;
    }
}

// ---------------- launch ----------------
extern "C" void kernel_launch(void* const* d_in, const int* in_sizes, int n_in,
                              void* d_out, int out_size)
{
    const float* x     = (const float*)d_in[0];
    const float* wih0f = (const float*)d_in[1];
    const float* whh0f = (const float*)d_in[2];
    const float* b0f   = (const float*)d_in[3];
    const float* wih0b = (const float*)d_in[4];
    const float* whh0b = (const float*)d_in[5];
    const float* b0b   = (const float*)d_in[6];
    const float* wih1f = (const float*)d_in[7];
    const float* whh1f = (const float*)d_in[8];
    const float* b1f   = (const float*)d_in[9];
    const float* wih1b = (const float*)d_in[10];
    const float* whh1b = (const float*)d_in[11];
    const float* b1b   = (const float*)d_in[12];
    const float* aw1   = (const float*)d_in[13];
    const float* ab1   = (const float*)d_in[14];
    const float* aw2   = (const float*)d_in[15];
    const float* ab2   = (const float*)d_in[16];
    const float* cw1   = (const float*)d_in[17];
    const float* cb1   = (const float*)d_in[18];
    const float* cw2   = (const float*)d_in[19];
    const float* cb2   = (const float*)d_in[20];
    float* out = (float*)d_out;

    float *xpf, *xpb, *h0, *lo, *awt, *sc, *aw, *ctx, *hc;
    cudaGetSymbolAddress((void**)&xpf, g_xpf);
    cudaGetSymbolAddress((void**)&xpb, g_xpb);
    cudaGetSymbolAddress((void**)&h0,  g_h0buf);
    cudaGetSymbolAddress((void**)&lo,  g_outbuf);
    cudaGetSymbolAddress((void**)&awt, g_awt);
    cudaGetSymbolAddress((void**)&sc,  g_scoresb);
    cudaGetSymbolAddress((void**)&aw,  g_attwb);
    cudaGetSymbolAddress((void**)&ctx, g_ctx);
    cudaGetSymbolAddress((void**)&hc,  g_hc);

    cudaFuncSetAttribute(gemm_mma<0, 0>, cudaFuncAttributeMaxDynamicSharedMemorySize, GSMEM);
    cudaFuncSetAttribute(gemm_mma<1, 0>, cudaFuncAttributeMaxDynamicSharedMemorySize, GSMEM);
    cudaFuncSetAttribute(gemm_mma<0, 1>, cudaFuncAttributeMaxDynamicSharedMemorySize, GSMEM);
    cudaFuncSetAttribute(lstm_mma, cudaFuncAttributeMaxDynamicSharedMemorySize, SMEM_LSTM);

    transpose_k<<<dim3(HD2 / 32, HD2 / 32), dim3(32, 32)>>>(aw1, awt, HD2, HD2);

    dim3 blk(256);
    dim3 gp(GG / 128, BT / 128);      // 16 x 256

    gemm_mma<0, 0><<<gp, blk, GSMEM>>>(x, wih0f, b0f, xpf, BT, GG, INN);
    gemm_mma<1, 0><<<gp, blk, GSMEM>>>(x, wih0b, b0b, xpb, BT, GG, INN);
    lstm_mma<<<128, 256, SMEM_LSTM>>>(xpf, xpb, whh0f, whh0b, h0);

    gemm_mma<0, 0><<<gp, blk, GSMEM>>>(h0, wih1f, b1f, xpf, BT, GG, HD2);
    gemm_mma<1, 0><<<gp, blk, GSMEM>>>(h0, wih1b, b1b, xpb, BT, GG, HD2);
    lstm_mma<<<128, 256, SMEM_LSTM>>>(xpf, xpb, whh1f, whh1b, lo);

    dim3 ga(HD2 / 128, BT / 128);     // 8 x 256
    gemm_mma<0, 1><<<ga, blk, GSMEM>>>(lo, awt, ab1, xpf, BT, HD2, HD2);
    scores_k<<<BT, 128>>>(xpf, aw2, ab2, sc);

    float* out_attw = (out_size >= (BB * NC + BT)) ? (out + BB * NC) : nullptr;
    softmax_k<<<BB, TT>>>(sc, aw, out_attw);
    context_k<<<dim3(HD2 / 256, BB), 256>>>(aw, lo, ctx);
    cls1_k<<<BB, 512>>>(ctx, cw1, cb1, hc);
    cls2_k<<<BB, 128>>>(hc, cw2, cb2, out);
}

// round 8
// speedup vs baseline: 2.9668x; 1.0429x over previous
#include <cuda_runtime.h>
#include <cstdint>

// Problem dims
#define BB   128      // batch
#define TT   256      // time
#define HH   512      // hidden
#define GG   2048     // 4H gates
#define INN  1662     // input features
#define HD2  1024     // 2H
#define NC   100      // classes
#define BT   32768    // B*T

// ---------------- device scratch ----------------
__device__ float g_xpf[BT * GG];
__device__ float g_xpb[BT * GG];
__device__ float g_h0buf[BT * HD2];       // layer0 h (tf32-rounded; GEMM A operand only)
__device__ float g_outbuf[BT * HD2];      // lstm_out fp32 (context/scores path)
__device__ float g_lor[BT * HD2];         // lstm_out tf32-rounded (attention GEMM A)
__device__ float g_awt[HD2 * HD2];        // aw1^T, rounded
__device__ float g_xr[BT * INN];          // x, rounded
__device__ float g_w0f[GG * INN];
__device__ float g_w0b[GG * INN];
__device__ float g_w1f[GG * HD2];
__device__ float g_w1b[GG * HD2];
__device__ float g_hping[4 * BB * HH];    // ping-pong h fp32: [ping][dir][B][H]
__device__ float g_scoresb[BT];
__device__ float g_attwb[BT];
__device__ float g_ctx[BB * HD2];
__device__ float g_hc[BB * HH];

// per-direction barrier state
__device__ unsigned g_bcnt2[2] = {0, 0};
__device__ unsigned g_bgen2[2] = {0, 0};

__device__ __forceinline__ uint32_t f2tf32(float x) {
    uint32_t u;
    asm("cvt.rna.tf32.f32 %0, %1;" : "=r"(u) : "f"(x));
    return u;
}

__device__ __forceinline__ void mma_tf32(float* d, const uint32_t* a, const uint32_t* b) {
    asm volatile(
        "mma.sync.aligned.m16n8k8.row.col.f32.tf32.tf32.f32 "
        "{%0,%1,%2,%3}, {%4,%5,%6,%7}, {%8,%9}, {%0,%1,%2,%3};"
        : "+f"(d[0]), "+f"(d[1]), "+f"(d[2]), "+f"(d[3])
        : "r"(a[0]), "r"(a[1]), "r"(a[2]), "r"(a[3]), "r"(b[0]), "r"(b[1]));
}

__device__ __forceinline__ uint32_t smem_u32(const void* p) {
    uint32_t a;
    asm("{ .reg .u64 t; cvta.to.shared.u64 t, %1; cvt.u32.u64 %0, t; }" : "=r"(a) : "l"(p));
    return a;
}
__device__ __forceinline__ void cp_async16(uint32_t dst, const void* src, int src_bytes) {
    asm volatile("cp.async.cg.shared.global [%0], [%1], 16, %2;"
                 :: "r"(dst), "l"(src), "r"(src_bytes) : "memory");
}
__device__ __forceinline__ void cp_async8(uint32_t dst, const void* src, int src_bytes) {
    asm volatile("cp.async.ca.shared.global [%0], [%1], 8, %2;"
                 :: "r"(dst), "l"(src), "r"(src_bytes) : "memory");
}
__device__ __forceinline__ void cp_commit() {
    asm volatile("cp.async.commit_group;" ::: "memory");
}
__device__ __forceinline__ void cp_wait0() {
    asm volatile("cp.async.wait_group 0;" ::: "memory");
}

// ---------------- rounding pass: dst = rna_tf32(src) ----------------
__global__ void round_k(const float4* __restrict__ src, float4* __restrict__ dst, int n4)
{
    int stride = gridDim.x * blockDim.x;
    for (int i = blockIdx.x * blockDim.x + threadIdx.x; i < n4; i += stride) {
        float4 v = src[i];
        v.x = __uint_as_float(f2tf32(v.x));
        v.y = __uint_as_float(f2tf32(v.y));
        v.z = __uint_as_float(f2tf32(v.z));
        v.w = __uint_as_float(f2tf32(v.w));
        dst[i] = v;
    }
}

// ---------------- tensor-core tf32 GEMM, cp.async double-buffered ----------------
// Inputs PRE-ROUNDED to tf32 (rna) -> fragment loads are plain LDS, no cvt.
// C[M,N] = act(A[M,K] * W[N,K]^T + bias).  Block tile 128x128, K chunk 32.
#define SSTR 36
#define GSMEM (2 * 2 * 128 * SSTR * 4)

template<int FLIP, int ACT>
__global__ __launch_bounds__(256, 2)
void gemm_mma(const float* __restrict__ A, const float* __restrict__ W,
              const float* __restrict__ bias, float* __restrict__ C,
              int M, int N, int K)
{
    extern __shared__ float dsm[];
    float* sA = dsm;                        // [2][128*SSTR]
    float* sB = dsm + 2 * 128 * SSTR;

    const int tid  = threadIdx.x;
    const int wid  = tid >> 5;
    const int lane = tid & 31;
    const int wm   = wid & 1;
    const int wn   = wid >> 1;
    const int m0 = blockIdx.y * 128;
    const int n0 = blockIdx.x * 128;
    const int lq = lane >> 2;
    const int lr = lane & 3;

    const uint32_t sA_base = smem_u32(sA);
    const uint32_t sB_base = smem_u32(sB);
    const bool use16 = ((K & 3) == 0);

    float acc[4][4][4];
#pragma unroll
    for (int i = 0; i < 4; i++)
#pragma unroll
        for (int j = 0; j < 4; j++)
#pragma unroll
            for (int r = 0; r < 4; r++) acc[i][j][r] = 0.f;

    const int nk = (K + 31) / 32;

    auto arow_of = [&](int r) {
        int gm = m0 + r;
        if (FLIP) { int bI = gm >> 8; int t = gm & 255; return (bI << 8) + (255 - t); }
        return gm;
    };

    auto load_chunk16 = [&](int kc, int buf) {
        const int k0 = kc * 32;
        const uint32_t boff = (uint32_t)buf * 128 * SSTR * 4;
#pragma unroll
        for (int i = 0; i < 4; i++) {
            int s  = tid + i * 256;
            int r  = s >> 3;
            int c4 = s & 7;
            int k  = k0 + c4 * 4;
            int nbf = K - k; nbf = nbf < 0 ? 0 : (nbf > 4 ? 4 : nbf);
            int bytes = nbf * 4;
            int ksrc = (k < K) ? k : 0;
            uint32_t soff = (uint32_t)(r * SSTR + c4 * 4) * 4;
            cp_async16(sA_base + boff + soff, A + (size_t)arow_of(r) * K + ksrc, bytes);
            cp_async16(sB_base + boff + soff, W + (size_t)(n0 + r) * K + ksrc, bytes);
        }
        cp_commit();
    };

    auto load_chunk8 = [&](int kc, int buf) {
        const int k0 = kc * 32;
        const uint32_t boff = (uint32_t)buf * 128 * SSTR * 4;
#pragma unroll
        for (int i = 0; i < 8; i++) {
            int s  = tid + i * 256;
            int r  = s >> 4;
            int c2 = s & 15;
            int k  = k0 + c2 * 2;
            int nbf = K - k; nbf = nbf < 0 ? 0 : (nbf > 2 ? 2 : nbf);
            int bytes = nbf * 4;
            int ksrc = (k < K) ? k : 0;
            uint32_t soff = (uint32_t)(r * SSTR + c2 * 2) * 4;
            cp_async8(sA_base + boff + soff, A + (size_t)arow_of(r) * K + ksrc, bytes);
            cp_async8(sB_base + boff + soff, W + (size_t)(n0 + r) * K + ksrc, bytes);
        }
        cp_commit();
    };

    auto load_chunk = [&](int kc, int buf) {
        if (use16) load_chunk16(kc, buf); else load_chunk8(kc, buf);
    };

    load_chunk(0, 0);

    for (int kc = 0; kc < nk; kc++) {
        cp_wait0();
        __syncthreads();
        if (kc + 1 < nk) load_chunk(kc + 1, (kc + 1) & 1);

        const float* bA = sA + (kc & 1) * 128 * SSTR;
        const float* bB = sB + (kc & 1) * 128 * SSTR;
#pragma unroll
        for (int ks = 0; ks < 4; ks++) {
            const int kb = ks * 8 + lr;
            uint32_t af[4][4];
#pragma unroll
            for (int mt = 0; mt < 4; mt++) {
                int base = wm * 64 + mt * 16 + lq;
                af[mt][0] = __float_as_uint(bA[ base      * SSTR + kb]);
                af[mt][1] = __float_as_uint(bA[(base + 8) * SSTR + kb]);
                af[mt][2] = __float_as_uint(bA[ base      * SSTR + kb + 4]);
                af[mt][3] = __float_as_uint(bA[(base + 8) * SSTR + kb + 4]);
            }
            uint32_t bf[4][2];
#pragma unroll
            for (int nt = 0; nt < 4; nt++) {
                int brow = wn * 32 + nt * 8 + lq;
                bf[nt][0] = __float_as_uint(bB[brow * SSTR + kb]);
                bf[nt][1] = __float_as_uint(bB[brow * SSTR + kb + 4]);
            }
#pragma unroll
            for (int mt = 0; mt < 4; mt++)
#pragma unroll
                for (int nt = 0; nt < 4; nt++)
                    mma_tf32(acc[mt][nt], af[mt], bf[nt]);
        }
        __syncthreads();
    }

    const int rbase = m0 + wm * 64;
    const int cbase = n0 + wn * 32;
#pragma unroll
    for (int mt = 0; mt < 4; mt++) {
#pragma unroll
        for (int nt = 0; nt < 4; nt++) {
            int c  = cbase + nt * 8 + lr * 2;
            float b0v = bias[c], b1v = bias[c + 1];
            int r0 = rbase + mt * 16 + lq;
            float v0 = acc[mt][nt][0] + b0v;
            float v1 = acc[mt][nt][1] + b1v;
            float v2 = acc[mt][nt][2] + b0v;
            float v3 = acc[mt][nt][3] + b1v;
            if (ACT == 1) { v0 = tanhf(v0); v1 = tanhf(v1); v2 = tanhf(v2); v3 = tanhf(v3); }
            *(float2*)(C + (size_t)r0 * N + c)       = make_float2(v0, v1);
            *(float2*)(C + (size_t)(r0 + 8) * N + c) = make_float2(v2, v3);
        }
    }
}

// ---------------- weight transpose with tf32 rounding ----------------
__global__ void transpose_k(const float* __restrict__ src, float* __restrict__ dst, int R, int Cc)
{
    __shared__ float t[32][33];
    int r0 = blockIdx.y * 32, c0 = blockIdx.x * 32;
    t[threadIdx.y][threadIdx.x] = src[(size_t)(r0 + threadIdx.y) * Cc + c0 + threadIdx.x];
    __syncthreads();
    dst[(size_t)(c0 + threadIdx.y) * R + r0 + threadIdx.x] =
        __uint_as_float(f2tf32(t[threadIdx.x][threadIdx.y]));
}

// ---------------- tensor-core persistent LSTM (3xTF32 split, cp.async h) ----------------
// Per-direction barriers (64 arrivals), arrive/wait split with xproj prefetch between.
// ROUND_OUT=1: hout receives tf32-rounded h (layer0 -> GEMM operand only).
#define WSTR 516
#define HSTR 68
#define SMEM_LSTM ((2 * 32 * WSTR) * 4 + (2 * 128 * HSTR) * 4)

__global__ __launch_bounds__(256, 1)
void lstm_mma(const float* __restrict__ xpF, const float* __restrict__ xpB,
              const float* __restrict__ whF, const float* __restrict__ whB,
              float* __restrict__ hout, float* __restrict__ houtr, int round_out)
{
    extern __shared__ uint32_t smem[];
    uint32_t* sWhi = smem;                      // 32 x WSTR (tf32)
    uint32_t* sWlo = smem + 32 * WSTR;
    float* sH = (float*)(smem + 2 * 32 * WSTR); // [2][128*HSTR] raw fp32
    __shared__ unsigned s_gen;

    const int tid  = threadIdx.x;
    const int bi   = blockIdx.x;
    const int w    = tid >> 5;
    const int lane = tid & 31;
    const int lq   = lane >> 2;
    const int lr   = lane & 3;
    const int dir  = bi >> 6;
    const int j0   = (bi & 63) * 8;
    const int w16  = w * 16;
    const float* wh = dir ? whB : whF;
    const float* xp = dir ? xpB : xpF;
    const uint32_t sH_base = smem_u32(sH);

    // load W tile (gate-row layout), split hi/lo once
    for (int e = tid; e < 32 * 512; e += 256) {
        int n = e >> 9, k = e & 511;
        int grow = (n >> 3) * 512 + j0 + (n & 7);
        float v = wh[(size_t)grow * HH + k];
        uint32_t hi = f2tf32(v);
        uint32_t lo = f2tf32(v - __uint_as_float(hi));
        sWhi[n * WSTR + k] = hi;
        sWlo[n * WSTR + k] = lo;
    }
    __syncthreads();

    float creg[4] = {0.f, 0.f, 0.f, 0.f};

    // prefetch xproj for t=0
    float2 xg2[2][4];
#pragma unroll
    for (int bb = 0; bb < 2; bb++) {
        const float* xr = xp + ((size_t)(w16 + lq + bb * 8) * TT + 0) * GG + j0 + lr * 2;
        xg2[bb][0] = *(const float2*)(xr);
        xg2[bb][1] = *(const float2*)(xr + 512);
        xg2[bb][2] = *(const float2*)(xr + 1024);
        xg2[bb][3] = *(const float2*)(xr + 1536);
    }

    for (int t = 0; t < TT; t++) {
        float acc[4][4];
#pragma unroll
        for (int nt = 0; nt < 4; nt++)
#pragma unroll
            for (int r = 0; r < 4; r++) acc[nt][r] = 0.f;

        if (t > 0) {
            const float* hprev = g_hping + ((((t - 1) & 1) << 1) + dir) * (BB * HH);

            auto load_hchunk = [&](int kc, int buf) {
                const uint32_t boff = (uint32_t)buf * 128 * HSTR * 4;
#pragma unroll
                for (int i = 0; i < 8; i++) {
                    int s   = tid + i * 256;
                    int row = s >> 4;
                    int c4  = s & 15;
                    cp_async16(sH_base + boff + (uint32_t)(row * HSTR + c4 * 4) * 4,
                               hprev + row * 512 + kc * 64 + c4 * 4, 16);
                }
                cp_commit();
            };

            load_hchunk(0, 0);
            for (int kc = 0; kc < 8; kc++) {
                cp_wait0();
                __syncthreads();
                if (kc < 7) load_hchunk(kc + 1, (kc + 1) & 1);

                const float* bH = sH + (kc & 1) * 128 * HSTR;
#pragma unroll
                for (int ks = 0; ks < 8; ks++) {
                    const int kk = ks * 8 + lr;
                    float v0 = bH[(w16 + lq)     * HSTR + kk];
                    float v1 = bH[(w16 + lq + 8) * HSTR + kk];
                    float v2 = bH[(w16 + lq)     * HSTR + kk + 4];
                    float v3 = bH[(w16 + lq + 8) * HSTR + kk + 4];
                    uint32_t ahi[4], alo[4];
                    ahi[0] = f2tf32(v0); alo[0] = f2tf32(v0 - __uint_as_float(ahi[0]));
                    ahi[1] = f2tf32(v1); alo[1] = f2tf32(v1 - __uint_as_float(ahi[1]));
                    ahi[2] = f2tf32(v2); alo[2] = f2tf32(v2 - __uint_as_float(ahi[2]));
                    ahi[3] = f2tf32(v3); alo[3] = f2tf32(v3 - __uint_as_float(ahi[3]));
                    const int kg = kc * 64 + kk;
#pragma unroll
                    for (int nt = 0; nt < 4; nt++) {
                        uint32_t bhi[2], blo[2];
                        bhi[0] = sWhi[(nt * 8 + lq) * WSTR + kg];
                        bhi[1] = sWhi[(nt * 8 + lq) * WSTR + kg + 4];
                        blo[0] = sWlo[(nt * 8 + lq) * WSTR + kg];
                        blo[1] = sWlo[(nt * 8 + lq) * WSTR + kg + 4];
                        mma_tf32(acc[nt], ahi, bhi);
                        mma_tf32(acc[nt], alo, bhi);
                        mma_tf32(acc[nt], ahi, blo);
                    }
                }
                __syncthreads();
            }
        }

        // epilogue: gates + c in registers
        const int tt = dir ? (TT - 1 - t) : t;
        float* hnext = g_hping + (((t & 1) << 1) + dir) * (BB * HH);
#pragma unroll
        for (int bb = 0; bb < 2; bb++) {
            int b = w16 + lq + bb * 8;
            int i0 = bb * 2;

            float zi = acc[0][i0] + xg2[bb][0].x, zf = acc[1][i0] + xg2[bb][1].x;
            float zg = acc[2][i0] + xg2[bb][2].x, zo = acc[3][i0] + xg2[bb][3].x;
            float si = 1.f / (1.f + __expf(-zi));
            float sf = 1.f / (1.f + __expf(-zf));
            float so = 1.f / (1.f + __expf(-zo));
            float tg = tanhf(zg);
            creg[i0] = sf * creg[i0] + si * tg;
            float h0v = so * tanhf(creg[i0]);

            zi = acc[0][i0 + 1] + xg2[bb][0].y; zf = acc[1][i0 + 1] + xg2[bb][1].y;
            zg = acc[2][i0 + 1] + xg2[bb][2].y; zo = acc[3][i0 + 1] + xg2[bb][3].y;
            si = 1.f / (1.f + __expf(-zi));
            sf = 1.f / (1.f + __expf(-zf));
            so = 1.f / (1.f + __expf(-zo));
            tg = tanhf(zg);
            creg[i0 + 1] = sf * creg[i0 + 1] + si * tg;
            float h1v = so * tanhf(creg[i0 + 1]);

            float2 hv = make_float2(h0v, h1v);
            *(float2*)(hnext + b * 512 + j0 + lr * 2) = hv;
            float2 ho = round_out
                ? make_float2(__uint_as_float(f2tf32(h0v)), __uint_as_float(f2tf32(h1v)))
                : hv;
            *(float2*)(hout + ((size_t)b * TT + tt) * HD2 + dir * 512 + j0 + lr * 2) = ho;
            if (houtr) {
                float2 hr = make_float2(__uint_as_float(f2tf32(h0v)), __uint_as_float(f2tf32(h1v)));
                *(float2*)(houtr + ((size_t)b * TT + tt) * HD2 + dir * 512 + j0 + lr * 2) = hr;
            }
        }

        // ---- barrier: arrive ----
        __syncthreads();
        if (tid == 0) {
            __threadfence();
            s_gen = atomicAdd(&g_bgen2[dir], 0u);
            if (atomicAdd(&g_bcnt2[dir], 1u) == 63u) {
                atomicExch(&g_bcnt2[dir], 0u);
                __threadfence();
                atomicAdd(&g_bgen2[dir], 1u);
            }
        }

        // ---- prefetch xproj for t+1 (independent of barrier) ----
        if (t + 1 < TT) {
#pragma unroll
            for (int bb = 0; bb < 2; bb++) {
                const float* xr = xp + ((size_t)(w16 + lq + bb * 8) * TT + (t + 1)) * GG + j0 + lr * 2;
                xg2[bb][0] = *(const float2*)(xr);
                xg2[bb][1] = *(const float2*)(xr + 512);
                xg2[bb][2] = *(const float2*)(xr + 1024);
                xg2[bb][3] = *(const float2*)(xr + 1536);
            }
        }

        // ---- barrier: wait ----
        if (tid == 0) {
            unsigned g = s_gen;
            while (atomicAdd(&g_bgen2[dir], 0u) == g) { __nanosleep(20); }
        }
        __syncthreads();
    }
}

// ---------------- tail kernels ----------------
__global__ void scores_k(const float* __restrict__ th, const float* __restrict__ aw2,
                         const float* __restrict__ ab2, float* __restrict__ sc)
{
    int r = blockIdx.x;
    const float* row = th + (size_t)r * HD2;
    float s = 0.f;
    for (int k = threadIdx.x; k < HD2; k += 128) s += row[k] * aw2[k];
    __shared__ float red[128];
    red[threadIdx.x] = s; __syncthreads();
    for (int o = 64; o > 0; o >>= 1) {
        if (threadIdx.x < o) red[threadIdx.x] += red[threadIdx.x + o];
        __syncthreads();
    }
    if (threadIdx.x == 0) sc[r] = red[0] + ab2[0];
}

__global__ void softmax_k(const float* __restrict__ sc, float* __restrict__ attw,
                          float* __restrict__ out_attw)
{
    int b = blockIdx.x, t = threadIdx.x;
    float v = sc[b * TT + t];
    __shared__ float red[TT];
    red[t] = v; __syncthreads();
    for (int o = 128; o > 0; o >>= 1) {
        if (t < o) red[t] = fmaxf(red[t], red[t + o]);
        __syncthreads();
    }
    float mx = red[0]; __syncthreads();
    float e = __expf(v - mx);
    red[t] = e; __syncthreads();
    for (int o = 128; o > 0; o >>= 1) {
        if (t < o) red[t] += red[t + o];
        __syncthreads();
    }
    float w = e / red[0];
    attw[b * TT + t] = w;
    if (out_attw) out_attw[b * TT + t] = w;
}

__global__ void context_k(const float* __restrict__ attw, const float* __restrict__ lo,
                          float* __restrict__ ctx)
{
    int b = blockIdx.y;
    int n = blockIdx.x * 256 + threadIdx.x;
    __shared__ float aw[TT];
    aw[threadIdx.x] = attw[b * TT + threadIdx.x];
    __syncthreads();
    float s = 0.f;
    const float* base = lo + (size_t)b * TT * HD2 + n;
#pragma unroll 4
    for (int t = 0; t < TT; t++) s += aw[t] * base[(size_t)t * HD2];
    ctx[b * HD2 + n] = s;
}

__global__ void cls1_k(const float* __restrict__ ctx, const float* __restrict__ w,
                       const float* __restrict__ bias, float* __restrict__ hc)
{
    int b = blockIdx.x, j = threadIdx.x;
    __shared__ float xs[HD2];
    xs[j] = ctx[b * HD2 + j];
    xs[j + 512] = ctx[b * HD2 + j + 512];
    __syncthreads();
    float s = bias[j];
    for (int k = 0; k < HD2; k++) s += xs[k] * w[k * HH + j];
    hc[b * HH + j] = fmaxf(s, 0.f);
}

__global__ void cls2_k(const float* __restrict__ hc, const float* __restrict__ w,
                       const float* __restrict__ bias, float* __restrict__ out)
{
    int b = blockIdx.x, j = threadIdx.x;
    __shared__ float xs[HH];
    for (int k = j; k < HH; k += 128) xs[k] = hc[b * HH + k];
    __syncthreads();
    if (j < NC) {
        float s = bias[j];
        for (int k = 0; k < HH; k++) s += xs[k] * w[k * NC + j];
        out[b * NC + j] = s;
    }
}

// ---------------- launch ----------------
extern "C" void kernel_launch(void* const* d_in, const int* in_sizes, int n_in,
                              void* d_out, int out_size)
{
    const float* x     = (const float*)d_in[0];
    const float* wih0f = (const float*)d_in[1];
    const float* whh0f = (const float*)d_in[2];
    const float* b0f   = (const float*)d_in[3];
    const float* wih0b = (const float*)d_in[4];
    const float* whh0b = (const float*)d_in[5];
    const float* b0b   = (const float*)d_in[6];
    const float* wih1f = (const float*)d_in[7];
    const float* whh1f = (const float*)d_in[8];
    const float* b1f   = (const float*)d_in[9];
    const float* wih1b = (const float*)d_in[10];
    const float* whh1b = (const float*)d_in[11];
    const float* b1b   = (const float*)d_in[12];
    const float* aw1   = (const float*)d_in[13];
    const float* ab1   = (const float*)d_in[14];
    const float* aw2   = (const float*)d_in[15];
    const float* ab2   = (const float*)d_in[16];
    const float* cw1   = (const float*)d_in[17];
    const float* cb1   = (const float*)d_in[18];
    const float* cw2   = (const float*)d_in[19];
    const float* cb2   = (const float*)d_in[20];
    float* out = (float*)d_out;

    float *xpf, *xpb, *h0, *lo, *lor, *awt, *xr, *w0f, *w0b, *w1f, *w1b, *sc, *aw, *ctx, *hc;
    cudaGetSymbolAddress((void**)&xpf, g_xpf);
    cudaGetSymbolAddress((void**)&xpb, g_xpb);
    cudaGetSymbolAddress((void**)&h0,  g_h0buf);
    cudaGetSymbolAddress((void**)&lo,  g_outbuf);
    cudaGetSymbolAddress((void**)&lor, g_lor);
    cudaGetSymbolAddress((void**)&awt, g_awt);
    cudaGetSymbolAddress((void**)&xr,  g_xr);
    cudaGetSymbolAddress((void**)&w0f, g_w0f);
    cudaGetSymbolAddress((void**)&w0b, g_w0b);
    cudaGetSymbolAddress((void**)&w1f, g_w1f);
    cudaGetSymbolAddress((void**)&w1b, g_w1b);
    cudaGetSymbolAddress((void**)&sc,  g_scoresb);
    cudaGetSymbolAddress((void**)&aw,  g_attwb);
    cudaGetSymbolAddress((void**)&ctx, g_ctx);
    cudaGetSymbolAddress((void**)&hc,  g_hc);

    cudaFuncSetAttribute(gemm_mma<0, 0>, cudaFuncAttributeMaxDynamicSharedMemorySize, GSMEM);
    cudaFuncSetAttribute(gemm_mma<1, 0>, cudaFuncAttributeMaxDynamicSharedMemorySize, GSMEM);
    cudaFuncSetAttribute(gemm_mma<0, 1>, cudaFuncAttributeMaxDynamicSharedMemorySize, GSMEM);
    cudaFuncSetAttribute(lstm_mma, cudaFuncAttributeMaxDynamicSharedMemorySize, SMEM_LSTM);

    // rounding passes (bit-identical to fragment-time cvt)
    round_k<<<1024, 256>>>((const float4*)x,     (float4*)xr,  BT * INN / 4);
    round_k<<<512, 256>>>((const float4*)wih0f, (float4*)w0f, GG * INN / 4);
    round_k<<<512, 256>>>((const float4*)wih0b, (float4*)w0b, GG * INN / 4);
    round_k<<<512, 256>>>((const float4*)wih1f, (float4*)w1f, GG * HD2 / 4);
    round_k<<<512, 256>>>((const float4*)wih1b, (float4*)w1b, GG * HD2 / 4);
    transpose_k<<<dim3(HD2 / 32, HD2 / 32), dim3(32, 32)>>>(aw1, awt, HD2, HD2);

    dim3 blk(256);
    dim3 gp(GG / 128, BT / 128);      // 16 x 256

    gemm_mma<0, 0><<<gp, blk, GSMEM>>>(xr, w0f, b0f, xpf, BT, GG, INN);
    gemm_mma<1, 0><<<gp, blk, GSMEM>>>(xr, w0b, b0b, xpb, BT, GG, INN);
    lstm_mma<<<128, 256, SMEM_LSTM>>>(xpf, xpb, whh0f, whh0b, h0, nullptr, 1);

    gemm_mma<0, 0><<<gp, blk, GSMEM>>>(h0, w1f, b1f, xpf, BT, GG, HD2);
    gemm_mma<1, 0><<<gp, blk, GSMEM>>>(h0, w1b, b1b, xpb, BT, GG, HD2);
    lstm_mma<<<128, 256, SMEM_LSTM>>>(xpf, xpb, whh1f, whh1b, lo, lor, 0);

    dim3 ga(HD2 / 128, BT / 128);     // 8 x 256
    gemm_mma<0, 1><<<ga, blk, GSMEM>>>(lor, awt, ab1, xpf, BT, HD2, HD2);
    scores_k<<<BT, 128>>>(xpf, aw2, ab2, sc);

    float* out_attw = (out_size >= (BB * NC + BT)) ? (out + BB * NC) : nullptr;
    softmax_k<<<BB, TT>>>(sc, aw, out_attw);
    context_k<<<dim3(HD2 / 256, BB), 256>>>(aw, lo, ctx);
    cls1_k<<<BB, 512>>>(ctx, cw1, cb1, hc);
    cls2_k<<<BB, 128>>>(hc, cw2, cb2, out);
}